// round 12
// baseline (speedup 1.0000x reference)
#include <cuda_runtime.h>
#include <cuda_fp16.h>
#include <math.h>
#include <stdint.h>

// ---------------- static config ----------------
#define BATCH 24
#define HH 60
#define WW 60
#define HP 63
#define WSZ 7
#define SSZ 3
#define NWIN 81          // 9x9 windows
#define NTOK 49          // tokens per window
#define DIM 256
#define NHEAD 8
#define HD 32
#define MW (BATCH*NWIN*NTOK)   // 95256 window tokens
#define MT (BATCH*HH*WW)       // 86400 real tokens

// GEMM tiling (mma.sync m16n8k16 fp16)
#define BM 128
#define BN 128
#define BK 64
#define AH 72                  // A smem row stride (halves) — LDSM conflict-free
#define BH 136                 // B smem row stride (halves) — LDSM.T conflict-free
#define STGH (BM*AH + BK*BH)   // halves per stage = 9216 + 8704 = 17920
#define NSTAGE 3
#define GEMM_SMEM (NSTAGE*STGH*2)   // 107520 bytes

// proj_fused tiling: BM=128 x BN2=256 (full row), 512 threads
#define BN2 256
#define PBH 264                // B smem row stride (halves)
#define PSTGH (BM*AH + BK*PBH) // 9216 + 16896 = 26112 halves
#define PROJ_SMEM (2*PSTGH*2)  // 104448 bytes

// ---------------- scratch (static device globals) ----------------
__device__ __half g_xh  [(size_t)MW*DIM];     // LN1 windowed output (fp16)
__device__ __half g_qkvh[(size_t)MW*3*DIM];   // qkv (fp16)
__device__ __half g_atth[(size_t)MW*DIM];     // attention output (fp16)
__device__ float  g_x1  [(size_t)MT*DIM];     // x + attn branch (fp32)
__device__ __half g_yh  [(size_t)MT*DIM];     // LN2 output (fp16)
__device__ __half g_hh  [(size_t)MT*4*DIM];   // fc1 output (fp16)
// fp16 weights
__device__ __half g_wq[256*768];
__device__ __half g_wp[256*256];
__device__ __half g_w1[256*1024];
__device__ __half g_w2[1024*256];

// ---------------- helpers ----------------
__device__ __forceinline__ uint32_t smem_u32(const void* p){
    return (uint32_t)__cvta_generic_to_shared((void*)p);
}
__device__ __forceinline__ void ldsm4(uint32_t* r, uint32_t addr){
    asm volatile("ldmatrix.sync.aligned.m8n8.x4.shared.b16 {%0,%1,%2,%3}, [%4];"
        : "=r"(r[0]),"=r"(r[1]),"=r"(r[2]),"=r"(r[3]) : "r"(addr));
}
__device__ __forceinline__ void ldsm4t(uint32_t* r, uint32_t addr){
    asm volatile("ldmatrix.sync.aligned.m8n8.x4.trans.shared.b16 {%0,%1,%2,%3}, [%4];"
        : "=r"(r[0]),"=r"(r[1]),"=r"(r[2]),"=r"(r[3]) : "r"(addr));
}
__device__ __forceinline__ void mma16816(float* c, const uint32_t* a, uint32_t b0, uint32_t b1){
    asm volatile("mma.sync.aligned.m16n8k16.row.col.f32.f16.f16.f32 "
        "{%0,%1,%2,%3}, {%4,%5,%6,%7}, {%8,%9}, {%0,%1,%2,%3};"
        : "+f"(c[0]),"+f"(c[1]),"+f"(c[2]),"+f"(c[3])
        : "r"(a[0]),"r"(a[1]),"r"(a[2]),"r"(a[3]), "r"(b0),"r"(b1));
}
__device__ __forceinline__ void cp16(uint32_t saddr, const void* g, int sz){
    asm volatile("cp.async.cg.shared.global [%0], [%1], 16, %2;"
                 :: "r"(saddr), "l"(g), "r"(sz) : "memory");
}
__device__ __forceinline__ float warp_sum(float v){
    #pragma unroll
    for (int o = 16; o; o >>= 1) v += __shfl_xor_sync(0xffffffffu, v, o);
    return v;
}
__device__ __forceinline__ int region_label(int p){
    return p < (HP - WSZ) ? 0 : (p < (HP - SSZ) ? 1 : 2);
}

// ---------------- fused fp32 -> fp16 weight conversion (all 4 weights) ----------------
// segments (half2 units): wq 98304, wp 32768, w1 131072, w2 131072 -> total 393216
__global__ void f2h_all(const float* __restrict__ s0, const float* __restrict__ s1,
                        const float* __restrict__ s2, const float* __restrict__ s3,
                        __half* __restrict__ d0, __half* __restrict__ d1,
                        __half* __restrict__ d2, __half* __restrict__ d3)
{
    int i = blockIdx.x*blockDim.x + threadIdx.x;
    if (i >= 393216) return;
    const float* s; __half* d; int off;
    if (i < 98304)        { s = s0; d = d0; off = i; }
    else if (i < 131072)  { s = s1; d = d1; off = i - 98304; }
    else if (i < 262144)  { s = s2; d = d2; off = i - 131072; }
    else                  { s = s3; d = d3; off = i - 262144; }
    float2 v = ((const float2*)s)[off];
    ((__half2*)d)[off] = __floats2half2_rn(v.x, v.y);
}

// ---------------- LN1 + pad + shift + window partition (fp16 out) ----------------
__global__ __launch_bounds__(256) void ln1_window_kernel(
    const float* __restrict__ x, const float* __restrict__ g, const float* __restrict__ b)
{
    int warp = (blockIdx.x * blockDim.x + threadIdx.x) >> 5;
    int lane = threadIdx.x & 31;
    if (warp >= MW) return;
    int bi  = warp / (NWIN*NTOK);
    int rem = warp - bi*(NWIN*NTOK);
    int w = rem / NTOK, n = rem - w*NTOK;
    int r = w/9, c = w - r*9, i = n/7, j = n - i*7;
    int hs = r*7 + i + SSZ; if (hs >= HP) hs -= HP;
    int ws = c*7 + j + SSZ; if (ws >= HP) ws -= HP;

    __half2* dst = (__half2*)(g_xh + (size_t)warp*DIM);
    if (hs >= HH || ws >= WW) {
        __half2 z = __floats2half2_rn(0.f, 0.f);
        dst[lane*2] = z; dst[lane*2+1] = z;
        dst[64+lane*2] = z; dst[64+lane*2+1] = z;
        return;
    }
    const float4* src = (const float4*)(x + ((size_t)bi*(HH*WW) + hs*WW + ws)*DIM);
    float4 v0 = src[lane], v1 = src[lane+32];
    float s  = v0.x+v0.y+v0.z+v0.w + v1.x+v1.y+v1.z+v1.w;
    float ss = v0.x*v0.x+v0.y*v0.y+v0.z*v0.z+v0.w*v0.w
             + v1.x*v1.x+v1.y*v1.y+v1.z*v1.z+v1.w*v1.w;
    s  = warp_sum(s);
    ss = warp_sum(ss);
    float mu   = s * (1.f/DIM);
    float var  = ss * (1.f/DIM) - mu*mu;
    float rstd = rsqrtf(var + 1e-5f);
    const float4* gv = (const float4*)g;
    const float4* bv = (const float4*)b;
    float4 g0 = gv[lane], g1 = gv[lane+32], b0 = bv[lane], b1 = bv[lane+32];
    dst[lane*2]      = __floats2half2_rn((v0.x-mu)*rstd*g0.x + b0.x, (v0.y-mu)*rstd*g0.y + b0.y);
    dst[lane*2+1]    = __floats2half2_rn((v0.z-mu)*rstd*g0.z + b0.z, (v0.w-mu)*rstd*g0.w + b0.w);
    dst[64+lane*2]   = __floats2half2_rn((v1.x-mu)*rstd*g1.x + b1.x, (v1.y-mu)*rstd*g1.y + b1.y);
    dst[64+lane*2+1] = __floats2half2_rn((v1.z-mu)*rstd*g1.z + b1.z, (v1.w-mu)*rstd*g1.w + b1.w);
}

// ---------------- fp16 mma.sync GEMM, BK=64, 3-stage cp.async + ldmatrix ----------------
template<int EPI, typename TOUT>
__global__ __launch_bounds__(256, 2) void hgemm(
    const __half* __restrict__ A, const __half* __restrict__ B,
    const float* __restrict__ bias, const float* __restrict__ Res,
    TOUT* __restrict__ C, int M, int N, int K)
{
    extern __shared__ __half sm[];
    const int tid = threadIdx.x;
    const int m0 = blockIdx.y * BM, n0 = blockIdx.x * BN;
    const int lane = tid & 31, warp = tid >> 5;
    const int wm = (warp >> 1) * 32;     // 4 warps along M
    const int wn = (warp & 1) * 64;      // 2 warps along N
    const int g = lane >> 2, t = lane & 3;
    const int lr = lane & 15, lc = lane >> 4;

    float acc[2][8][4];
    #pragma unroll
    for (int mi = 0; mi < 2; mi++)
        #pragma unroll
        for (int ni = 0; ni < 8; ni++)
            #pragma unroll
            for (int q = 0; q < 4; q++) acc[mi][ni][q] = 0.f;

    const uint32_t sbase = smem_u32(sm);

    auto issue = [&](int kc, int s){
        const int k0 = kc * BK;
        #pragma unroll
        for (int i = 0; i < 4; i++){
            int f = tid + i*256;
            int row = f >> 3, q = f & 7;
            int gr = m0 + row;
            int cl = gr < M ? gr : (M - 1);
            const __half* src = A + (size_t)cl*K + k0 + q*8;
            cp16(sbase + (uint32_t)((s*STGH + row*AH + q*8)*2), src, gr < M ? 16 : 0);
        }
        #pragma unroll
        for (int i = 0; i < 4; i++){
            int f = tid + i*256;
            int row = f >> 4, q = f & 15;
            const __half* src = B + (size_t)(k0 + row)*N + n0 + q*8;
            cp16(sbase + (uint32_t)((s*STGH + BM*AH + row*BH + q*8)*2), src, 16);
        }
        asm volatile("cp.async.commit_group;" ::: "memory");
    };

    const int nch = K / BK;
    issue(0, 0);
    if (nch > 1) issue(1, 1);
    int s = 0;
    for (int kc = 0; kc < nch; kc++){
        if (kc + 1 < nch){
            asm volatile("cp.async.wait_group 1;" ::: "memory");
        } else {
            asm volatile("cp.async.wait_group 0;" ::: "memory");
        }
        __syncthreads();
        if (kc + 2 < nch){
            int s2 = s + 2; if (s2 >= NSTAGE) s2 -= NSTAGE;
            issue(kc + 2, s2);
        }
        const uint32_t sa = sbase + (uint32_t)(s*STGH)*2;
        const uint32_t sb = sbase + (uint32_t)(s*STGH + BM*AH)*2;
        #pragma unroll
        for (int kk = 0; kk < 4; kk++){
            uint32_t af[2][4];
            #pragma unroll
            for (int mi = 0; mi < 2; mi++)
                ldsm4(af[mi], sa + (uint32_t)(((wm + mi*16 + lr)*AH + kk*16 + lc*8)*2));
            #pragma unroll
            for (int nb = 0; nb < 4; nb++){
                uint32_t bf[4];
                ldsm4t(bf, sb + (uint32_t)(((kk*16 + lr)*BH + wn + nb*16 + lc*8)*2));
                mma16816(acc[0][nb*2+0], af[0], bf[0], bf[1]);
                mma16816(acc[1][nb*2+0], af[1], bf[0], bf[1]);
                mma16816(acc[0][nb*2+1], af[0], bf[2], bf[3]);
                mma16816(acc[1][nb*2+1], af[1], bf[2], bf[3]);
            }
        }
        if (++s >= NSTAGE) s = 0;
    }

    #pragma unroll
    for (int mi = 0; mi < 2; mi++){
        const int r0 = m0 + wm + mi*16 + g;
        #pragma unroll
        for (int half = 0; half < 2; half++){
            const int gr = r0 + half*8;
            if (gr < M){
                #pragma unroll
                for (int ni = 0; ni < 8; ni++){
                    const int col = n0 + wn + ni*8 + t*2;
                    float2 bb = *(const float2*)(bias + col);
                    float v0 = acc[mi][ni][half*2 + 0] + bb.x;
                    float v1 = acc[mi][ni][half*2 + 1] + bb.y;
                    if (EPI == 1){
                        v0 = 0.5f*v0*(1.f + erff(v0*0.70710678118654752f));
                        v1 = 0.5f*v1*(1.f + erff(v1*0.70710678118654752f));
                    }
                    if (EPI == 2){
                        float2 rr = *(const float2*)(Res + (size_t)gr*N + col);
                        v0 += rr.x; v1 += rr.y;
                    }
                    if (sizeof(TOUT) == 2){
                        *(__half2*)((__half*)C + (size_t)gr*N + col) = __floats2half2_rn(v0, v1);
                    } else {
                        *(float2*)((float*)C + (size_t)gr*N + col) = make_float2(v0, v1);
                    }
                }
            }
        }
    }
}

// ---------------- fused proj GEMM + window-reverse + residual + LN2 ----------------
// C = attn[MW,256] @ w_proj[256,256]; per-row: token = unshift(window row);
// x1 = x[token] + C  (fp32, token layout); y = LN(x1)*g2+b2 (fp16, token layout)
__global__ __launch_bounds__(512, 1) void proj_fused(
    const __half* __restrict__ A, const __half* __restrict__ B,
    const float* __restrict__ bias, const float* __restrict__ xres,
    const float* __restrict__ gam, const float* __restrict__ bet)
{
    extern __shared__ __half sm[];
    const int tid = threadIdx.x;
    const int m0 = blockIdx.x * BM;
    const int lane = tid & 31, warp = tid >> 5;
    const int wm = (warp >> 2) * 32;     // 4 warps along M
    const int wn = (warp & 3) * 64;      // 4 warps along N (covers 256)
    const int g = lane >> 2, t = lane & 3;
    const int lr = lane & 15, lc = lane >> 4;

    float acc[2][8][4];
    #pragma unroll
    for (int mi = 0; mi < 2; mi++)
        #pragma unroll
        for (int ni = 0; ni < 8; ni++)
            #pragma unroll
            for (int q = 0; q < 4; q++) acc[mi][ni][q] = 0.f;

    const uint32_t sbase = smem_u32(sm);

    auto issue = [&](int kc, int s){
        const int k0 = kc * BK;
        // A tile: 128 rows x 64 halves = 8 chunks/row -> 1024 chunks / 512 thr
        #pragma unroll
        for (int i = 0; i < 2; i++){
            int f = tid + i*512;
            int row = f >> 3, q = f & 7;
            int gr = m0 + row;
            int cl = gr < MW ? gr : (MW - 1);
            const __half* src = A + (size_t)cl*DIM + k0 + q*8;
            cp16(sbase + (uint32_t)((s*PSTGH + row*AH + q*8)*2), src, gr < MW ? 16 : 0);
        }
        // B tile: 64 rows x 256 halves = 32 chunks/row -> 2048 chunks / 512 thr
        #pragma unroll
        for (int i = 0; i < 4; i++){
            int f = tid + i*512;
            int row = f >> 5, q = f & 31;
            const __half* src = B + (size_t)(k0 + row)*BN2 + q*8;
            cp16(sbase + (uint32_t)((s*PSTGH + BM*AH + row*PBH + q*8)*2), src, 16);
        }
        asm volatile("cp.async.commit_group;" ::: "memory");
    };

    const int nch = DIM / BK;   // 4
    issue(0, 0);
    for (int kc = 0; kc < nch; kc++){
        const int s = kc & 1;
        if (kc + 1 < nch){
            issue(kc + 1, s ^ 1);
            asm volatile("cp.async.wait_group 1;" ::: "memory");
        } else {
            asm volatile("cp.async.wait_group 0;" ::: "memory");
        }
        __syncthreads();
        const uint32_t sa = sbase + (uint32_t)(s*PSTGH)*2;
        const uint32_t sb = sbase + (uint32_t)(s*PSTGH + BM*AH)*2;
        #pragma unroll
        for (int kk = 0; kk < 4; kk++){
            uint32_t af[2][4];
            #pragma unroll
            for (int mi = 0; mi < 2; mi++)
                ldsm4(af[mi], sa + (uint32_t)(((wm + mi*16 + lr)*AH + kk*16 + lc*8)*2));
            #pragma unroll
            for (int nb = 0; nb < 4; nb++){
                uint32_t bf[4];
                ldsm4t(bf, sb + (uint32_t)(((kk*16 + lr)*PBH + wn + nb*16 + lc*8)*2));
                mma16816(acc[0][nb*2+0], af[0], bf[0], bf[1]);
                mma16816(acc[1][nb*2+0], af[1], bf[0], bf[1]);
                mma16816(acc[0][nb*2+1], af[0], bf[2], bf[3]);
                mma16816(acc[1][nb*2+1], af[1], bf[2], bf[3]);
            }
        }
        __syncthreads();
    }

    // ---- fused epilogue: residual gather + LN over full 256-wide rows ----
    float* red = (float*)sm;   // [128][8]: per row, 4 warpN x {sum, sumsq}
    const int warpN = warp & 3;

    int   tok[2][2];
    bool  valid[2][2];
    float lsum[2][2], lsq[2][2];

    #pragma unroll
    for (int mi = 0; mi < 2; mi++){
        #pragma unroll
        for (int half = 0; half < 2; half++){
            int row = wm + mi*16 + half*8 + g;
            int gm = m0 + row;
            bool v = gm < MW;
            int token = 0;
            if (v){
                int bi = gm / (NWIN*NTOK);
                int rem = gm - bi*(NWIN*NTOK);
                int w = rem / NTOK, n = rem - w*NTOK;
                int r = w/9, cc = w - r*9, i = n/7, j = n - i*7;
                int hh = r*7 + i + SSZ; if (hh >= HP) hh -= HP;
                int ww2 = cc*7 + j + SSZ; if (ww2 >= HP) ww2 -= HP;
                if (hh >= HH || ww2 >= WW) v = false;
                else token = bi*(HH*WW) + hh*WW + ww2;
            }
            tok[mi][half] = token;
            valid[mi][half] = v;
            // add bias + residual into acc (in place), accumulate row stats
            float ls = 0.f, lq = 0.f;
            #pragma unroll
            for (int ni = 0; ni < 8; ni++){
                int col = wn + ni*8 + t*2;
                float2 bb = *(const float2*)(bias + col);
                float2 xr = v ? *(const float2*)(xres + (size_t)token*DIM + col)
                              : make_float2(0.f, 0.f);
                float v0 = acc[mi][ni][half*2 + 0] + bb.x + xr.x;
                float v1 = acc[mi][ni][half*2 + 1] + bb.y + xr.y;
                acc[mi][ni][half*2 + 0] = v0;
                acc[mi][ni][half*2 + 1] = v1;
                ls += v0 + v1;
                lq += v0*v0 + v1*v1;
            }
            // reduce over t (lanes g*4 + {0..3})
            ls += __shfl_xor_sync(0xffffffffu, ls, 1);
            ls += __shfl_xor_sync(0xffffffffu, ls, 2);
            lq += __shfl_xor_sync(0xffffffffu, lq, 1);
            lq += __shfl_xor_sync(0xffffffffu, lq, 2);
            lsum[mi][half] = ls; lsq[mi][half] = lq;
            if (t == 0){
                red[row*8 + warpN*2 + 0] = ls;
                red[row*8 + warpN*2 + 1] = lq;
            }
        }
    }
    __syncthreads();

    #pragma unroll
    for (int mi = 0; mi < 2; mi++){
        #pragma unroll
        for (int half = 0; half < 2; half++){
            if (!valid[mi][half]) continue;
            int row = wm + mi*16 + half*8 + g;
            float s = 0.f, q = 0.f;
            #pragma unroll
            for (int wn4 = 0; wn4 < 4; wn4++){
                s += red[row*8 + wn4*2 + 0];
                q += red[row*8 + wn4*2 + 1];
            }
            float mu   = s * (1.f/DIM);
            float var  = q * (1.f/DIM) - mu*mu;
            float rstd = rsqrtf(var + 1e-5f);
            int token = tok[mi][half];
            float*  x1d = g_x1 + (size_t)token*DIM;
            __half* yd  = g_yh + (size_t)token*DIM;
            #pragma unroll
            for (int ni = 0; ni < 8; ni++){
                int col = wn + ni*8 + t*2;
                float v0 = acc[mi][ni][half*2 + 0];
                float v1 = acc[mi][ni][half*2 + 1];
                *(float2*)(x1d + col) = make_float2(v0, v1);
                float2 gg = *(const float2*)(gam + col);
                float2 bb = *(const float2*)(bet + col);
                *(__half2*)(yd + col) = __floats2half2_rn(
                    (v0 - mu)*rstd*gg.x + bb.x, (v1 - mu)*rstd*gg.y + bb.y);
            }
        }
    }
}

// ---------------- attention via fp16 tensor cores + ldmatrix ----------------
#define QH 40   // Q/K/V smem row stride (halves) — LDSM conflict-free
#define PH 72   // P smem row stride (halves)     — LDSM conflict-free
__global__ __launch_bounds__(128) void attn_kernel(const float* __restrict__ relt)
{
    __shared__ __half Qs[64][QH];
    __shared__ __half Ks[64][QH];
    __shared__ __half Vs[64][QH];
    __shared__ __half Ps[64][PH];
    __shared__ float  Ss[64][68];

    const int tid = threadIdx.x;
    const int warp = tid >> 5, lane = tid & 31;
    const int g = lane >> 2, t = lane & 3;
    const int lr = lane & 15, lc = lane >> 4;
    const int wh  = blockIdx.x;
    const int win = wh >> 3;
    const int h   = wh & 7;

    const __half* base = g_qkvh + (size_t)win*NTOK*(3*DIM) + h*HD;
    for (int e = tid; e < 64*16; e += 128){
        int n = e >> 4, d = e & 15;
        __half2 q, k, v;
        if (n < NTOK){
            const __half2* row = (const __half2*)(base + (size_t)n*(3*DIM));
            q = row[d]; k = row[(DIM>>1) + d]; v = row[DIM + d];
        } else {
            q = __floats2half2_rn(0.f,0.f); k = q; v = q;
        }
        *(__half2*)&Qs[n][d*2] = q;
        *(__half2*)&Ks[n][d*2] = k;
        *(__half2*)&Vs[n][d*2] = v;
    }
    __syncthreads();

    float accs[8][4];
    #pragma unroll
    for (int ni = 0; ni < 8; ni++)
        #pragma unroll
        for (int q = 0; q < 4; q++) accs[ni][q] = 0.f;

    const uint32_t qb = smem_u32(Qs), kb = smem_u32(Ks);
    #pragma unroll
    for (int kk = 0; kk < 2; kk++){
        uint32_t a[4];
        ldsm4(a, qb + (uint32_t)(((16*warp + lr)*QH + kk*16 + lc*8)*2));
        #pragma unroll
        for (int nb = 0; nb < 4; nb++){
            uint32_t b[4];
            ldsm4(b, kb + (uint32_t)(((nb*16 + lr)*QH + kk*16 + lc*8)*2));
            mma16816(accs[nb*2+0], a, b[0], b[2]);
            mma16816(accs[nb*2+1], a, b[1], b[3]);
        }
    }

    const int w  = win % NWIN;
    const int wr = w / 9, wc = w - (w/9)*9;
    const float scale = 0.17677669529663687f;   // 1/sqrt(32)
    #pragma unroll
    for (int ni = 0; ni < 8; ni++){
        #pragma unroll
        for (int half = 0; half < 2; half++){
            int row = 16*warp + half*8 + g;
            int c0 = ni*8 + t*2;
            float v0 = accs[ni][half*2 + 0] * scale;
            float v1 = accs[ni][half*2 + 1] * scale;
            if (row < NTOK){
                int in_ = row/7, jn = row - (row/7)*7;
                int rn = region_label(wr*7 + in_)*3 + region_label(wc*7 + jn);
                if (c0 < NTOK){
                    int im = c0/7, jm = c0 - (c0/7)*7;
                    v0 += __ldg(&relt[((in_ - im + 6)*13 + (jn - jm + 6))*NHEAD + h]);
                    int rm = region_label(wr*7 + im)*3 + region_label(wc*7 + jm);
                    if (rn != rm) v0 -= 100.f;
                }
                if (c0 + 1 < NTOK){
                    int c1 = c0 + 1;
                    int im = c1/7, jm = c1 - (c1/7)*7;
                    v1 += __ldg(&relt[((in_ - im + 6)*13 + (jn - jm + 6))*NHEAD + h]);
                    int rm = region_label(wr*7 + im)*3 + region_label(wc*7 + jm);
                    if (rn != rm) v1 -= 100.f;
                }
            }
            Ss[row][c0]     = v0;
            Ss[row][c0 + 1] = v1;
        }
    }
    __syncthreads();

    if (tid < NTOK){
        float mx = -1e30f;
        #pragma unroll
        for (int m = 0; m < NTOK; m++) mx = fmaxf(mx, Ss[tid][m]);
        float s = 0.f;
        float e[NTOK];
        #pragma unroll
        for (int m = 0; m < NTOK; m++){ e[m] = __expf(Ss[tid][m] - mx); s += e[m]; }
        float inv = 1.f / s;
        #pragma unroll
        for (int m = 0; m < NTOK; m += 2){
            float p0 = e[m]*inv;
            float p1 = (m+1 < NTOK) ? e[m+1]*inv : 0.f;
            *(__half2*)&Ps[tid][m] = __floats2half2_rn(p0, p1);
        }
        #pragma unroll
        for (int m = NTOK+1; m < 64; m += 2)
            *(__half2*)&Ps[tid][m] = __floats2half2_rn(0.f, 0.f);
    } else if (tid >= 64 && tid < 64 + (64 - NTOK)){
        int row = NTOK + (tid - 64);
        #pragma unroll
        for (int m = 0; m < 64; m += 2)
            *(__half2*)&Ps[row][m] = __floats2half2_rn(0.f, 0.f);
    }
    __syncthreads();

    float acco[4][4];
    #pragma unroll
    for (int ni = 0; ni < 4; ni++)
        #pragma unroll
        for (int q = 0; q < 4; q++) acco[ni][q] = 0.f;

    const uint32_t pb = smem_u32(Ps), vb = smem_u32(Vs);
    #pragma unroll
    for (int kk = 0; kk < 4; kk++){
        uint32_t a[4];
        ldsm4(a, pb + (uint32_t)(((16*warp + lr)*PH + kk*16 + lc*8)*2));
        #pragma unroll
        for (int nb = 0; nb < 2; nb++){
            uint32_t b[4];
            ldsm4t(b, vb + (uint32_t)(((kk*16 + lr)*QH + nb*16 + lc*8)*2));
            mma16816(acco[nb*2+0], a, b[0], b[1]);
            mma16816(acco[nb*2+1], a, b[2], b[3]);
        }
    }

    __half* out = g_atth + (size_t)win*NTOK*DIM + h*HD;
    #pragma unroll
    for (int ni = 0; ni < 4; ni++){
        #pragma unroll
        for (int half = 0; half < 2; half++){
            int row = 16*warp + half*8 + g;
            if (row < NTOK){
                int col = ni*8 + t*2;
                *(__half2*)(out + (size_t)row*DIM + col) =
                    __floats2half2_rn(acco[ni][half*2 + 0], acco[ni][half*2 + 1]);
            }
        }
    }
}

// ---------------- host launcher ----------------
extern "C" void kernel_launch(void* const* d_in, const int* in_sizes, int n_in,
                              void* d_out, int out_size)
{
    (void)in_sizes; (void)n_in; (void)out_size;
    const float* x      = (const float*)d_in[0];
    const float* g1     = (const float*)d_in[1];
    const float* b1     = (const float*)d_in[2];
    const float* w_qkv  = (const float*)d_in[3];
    const float* b_qkv  = (const float*)d_in[4];
    const float* relt   = (const float*)d_in[5];
    const float* w_proj = (const float*)d_in[6];
    const float* b_proj = (const float*)d_in[7];
    const float* g2     = (const float*)d_in[8];
    const float* b2     = (const float*)d_in[9];
    const float* w_fc1  = (const float*)d_in[10];
    const float* b_fc1  = (const float*)d_in[11];
    const float* w_fc2  = (const float*)d_in[12];
    const float* b_fc2  = (const float*)d_in[13];
    float* out = (float*)d_out;

    __half *p_xh, *p_qkvh, *p_atth, *p_yh, *p_hh, *p_wq, *p_wp, *p_w1, *p_w2;
    float *p_x1;
    cudaGetSymbolAddress((void**)&p_xh,  g_xh);
    cudaGetSymbolAddress((void**)&p_qkvh,g_qkvh);
    cudaGetSymbolAddress((void**)&p_atth,g_atth);
    cudaGetSymbolAddress((void**)&p_x1,  g_x1);
    cudaGetSymbolAddress((void**)&p_yh,  g_yh);
    cudaGetSymbolAddress((void**)&p_hh,  g_hh);
    cudaGetSymbolAddress((void**)&p_wq,  g_wq);
    cudaGetSymbolAddress((void**)&p_wp,  g_wp);
    cudaGetSymbolAddress((void**)&p_w1,  g_w1);
    cudaGetSymbolAddress((void**)&p_w2,  g_w2);

    cudaFuncSetAttribute(hgemm<0,__half>, cudaFuncAttributeMaxDynamicSharedMemorySize, GEMM_SMEM);
    cudaFuncSetAttribute(hgemm<1,__half>, cudaFuncAttributeMaxDynamicSharedMemorySize, GEMM_SMEM);
    cudaFuncSetAttribute(hgemm<2,float>,  cudaFuncAttributeMaxDynamicSharedMemorySize, GEMM_SMEM);
    cudaFuncSetAttribute(proj_fused,      cudaFuncAttributeMaxDynamicSharedMemorySize, PROJ_SMEM);

    // 0) weights -> fp16 (single fused launch)
    f2h_all<<<(393216 + 255)/256, 256>>>(w_qkv, w_proj, w_fc1, w_fc2, p_wq, p_wp, p_w1, p_w2);

    // 1) LN1 + pad + shift + window partition (fp16)
    ln1_window_kernel<<<(MW*32 + 255)/256, 256>>>(x, g1, b1);

    // 2) QKV GEMM [MW,256]x[256,768] -> fp16
    hgemm<0,__half><<<dim3(768/BN, (MW + BM - 1)/BM), 256, GEMM_SMEM>>>(
        p_xh, p_wq, b_qkv, (const float*)0, p_qkvh, MW, 768, 256);

    // 3) attention (fp16 MMA) -> fp16
    attn_kernel<<<BATCH*NWIN*NHEAD, 128>>>(relt);

    // 4) proj GEMM + window-reverse + residual + LN2 (fused) -> g_x1 (fp32), g_yh (fp16)
    proj_fused<<<(MW + BM - 1)/BM, 512, PROJ_SMEM>>>(
        p_atth, p_wp, b_proj, x, g2, b2);

    // 5) fc1 + GELU [MT,256]x[256,1024] -> fp16
    hgemm<1,__half><<<dim3(1024/BN, MT/BM), 256, GEMM_SMEM>>>(
        p_yh, p_w1, b_fc1, (const float*)0, p_hh, MT, 1024, 256);

    // 6) fc2 + bias + residual [MT,1024]x[1024,256] -> out fp32
    hgemm<2,float><<<dim3(256/BN, MT/BM), 256, GEMM_SMEM>>>(
        p_hh, p_w2, b_fc2, p_x1, out, MT, 256, 1024);
}

// round 14
// speedup vs baseline: 1.1109x; 1.1109x over previous
#include <cuda_runtime.h>
#include <cuda_fp16.h>
#include <math.h>
#include <stdint.h>

// ---------------- static config ----------------
#define BATCH 24
#define HH 60
#define WW 60
#define HP 63
#define WSZ 7
#define SSZ 3
#define NWIN 81          // 9x9 windows
#define NTOK 49          // tokens per window
#define DIM 256
#define NHEAD 8
#define HD 32
#define MW (BATCH*NWIN*NTOK)   // 95256 window tokens
#define MT (BATCH*HH*WW)       // 86400 real tokens

// GEMM tiling (mma.sync m16n8k16 fp16)
#define BM 128
#define BN 128
#define BK 64
#define AH 72                  // A smem row stride (halves) — LDSM conflict-free
#define BH 136                 // B smem row stride (halves) — LDSM.T conflict-free
#define STGH (BM*AH + BK*BH)   // halves per stage = 9216 + 8704 = 17920
#define NSTAGE 3
#define GEMM_SMEM (NSTAGE*STGH*2)   // 107520 bytes

// ---------------- scratch (static device globals) ----------------
__device__ __half g_xh  [(size_t)MW*DIM];     // LN1 windowed output (fp16)
__device__ __half g_qkvh[(size_t)MW*3*DIM];   // qkv (fp16)
__device__ __half g_atth[(size_t)MW*DIM];     // attention output (fp16)
__device__ __half g_projh[(size_t)MW*DIM];    // proj output (fp16, window layout)
__device__ float  g_x1  [(size_t)MT*DIM];     // x + attn branch (fp32)
__device__ __half g_yh  [(size_t)MT*DIM];     // LN2 output (fp16)
__device__ __half g_hh  [(size_t)MT*4*DIM];   // fc1 output (fp16)
// fp16 weights
__device__ __half g_wq[256*768];
__device__ __half g_wp[256*256];
__device__ __half g_w1[256*1024];
__device__ __half g_w2[1024*256];
// precomputed attention bias+mask table: [variant][head][64][64] fp32
__device__ float g_bias[4*NHEAD*64*64];

// ---------------- helpers ----------------
__device__ __forceinline__ uint32_t smem_u32(const void* p){
    return (uint32_t)__cvta_generic_to_shared((void*)p);
}
__device__ __forceinline__ void ldsm4(uint32_t* r, uint32_t addr){
    asm volatile("ldmatrix.sync.aligned.m8n8.x4.shared.b16 {%0,%1,%2,%3}, [%4];"
        : "=r"(r[0]),"=r"(r[1]),"=r"(r[2]),"=r"(r[3]) : "r"(addr));
}
__device__ __forceinline__ void ldsm4t(uint32_t* r, uint32_t addr){
    asm volatile("ldmatrix.sync.aligned.m8n8.x4.trans.shared.b16 {%0,%1,%2,%3}, [%4];"
        : "=r"(r[0]),"=r"(r[1]),"=r"(r[2]),"=r"(r[3]) : "r"(addr));
}
__device__ __forceinline__ void mma16816(float* c, const uint32_t* a, uint32_t b0, uint32_t b1){
    asm volatile("mma.sync.aligned.m16n8k16.row.col.f32.f16.f16.f32 "
        "{%0,%1,%2,%3}, {%4,%5,%6,%7}, {%8,%9}, {%0,%1,%2,%3};"
        : "+f"(c[0]),"+f"(c[1]),"+f"(c[2]),"+f"(c[3])
        : "r"(a[0]),"r"(a[1]),"r"(a[2]),"r"(a[3]), "r"(b0),"r"(b1));
}
__device__ __forceinline__ void cp16(uint32_t saddr, const void* g, int sz){
    asm volatile("cp.async.cg.shared.global [%0], [%1], 16, %2;"
                 :: "r"(saddr), "l"(g), "r"(sz) : "memory");
}
__device__ __forceinline__ float warp_sum(float v){
    #pragma unroll
    for (int o = 16; o; o >>= 1) v += __shfl_xor_sync(0xffffffffu, v, o);
    return v;
}

// ---------------- fused fp32 -> fp16 weight conversion (all 4 weights) ----------------
__global__ void f2h_all(const float* __restrict__ s0, const float* __restrict__ s1,
                        const float* __restrict__ s2, const float* __restrict__ s3,
                        __half* __restrict__ d0, __half* __restrict__ d1,
                        __half* __restrict__ d2, __half* __restrict__ d3)
{
    int i = blockIdx.x*blockDim.x + threadIdx.x;
    if (i >= 393216) return;
    const float* s; __half* d; int off;
    if (i < 98304)        { s = s0; d = d0; off = i; }
    else if (i < 131072)  { s = s1; d = d1; off = i - 98304; }
    else if (i < 262144)  { s = s2; d = d2; off = i - 131072; }
    else                  { s = s3; d = d3; off = i - 262144; }
    float2 v = ((const float2*)s)[off];
    ((__half2*)d)[off] = __floats2half2_rn(v.x, v.y);
}

// ---------------- bias+mask table precompute: [variant][head][64][64] ----------------
// variant: bit0 = row-masked (wr==8), bit1 = col-masked (wc==8)
__global__ void bias_table_kernel(const float* __restrict__ relt)
{
    int v = blockIdx.x >> 3, h = blockIdx.x & 7;
    bool rm = (v & 1) != 0, cm = (v & 2) != 0;
    float* dst = g_bias + (size_t)(v*NHEAD + h)*64*64;
    for (int e = threadIdx.x; e < 64*64; e += 128){
        int n = e >> 6, m = e & 63;
        float val;
        if (m >= NTOK){
            val = -20000.f;                 // pad col: exp -> 0
        } else {
            int nn = n < NTOK ? n : NTOK - 1;   // pad rows: harmless copy
            int in_ = nn/7, jn = nn - in_*7;
            int im  = m/7,  jm = m  - im*7;
            val = relt[((in_ - im + 6)*13 + (jn - jm + 6))*NHEAD + h];
            int rn = (rm ? (in_ < 4 ? 1 : 2) : 0)*3 + (cm ? (jn < 4 ? 1 : 2) : 0);
            int rmm= (rm ? (im  < 4 ? 1 : 2) : 0)*3 + (cm ? (jm  < 4 ? 1 : 2) : 0);
            if (rn != rmm) val -= 100.f;
        }
        dst[e] = val;
    }
}

// ---------------- LN1 + pad + shift + window partition (fp16 out) ----------------
__global__ __launch_bounds__(256) void ln1_window_kernel(
    const float* __restrict__ x, const float* __restrict__ g, const float* __restrict__ b)
{
    int warp = (blockIdx.x * blockDim.x + threadIdx.x) >> 5;
    int lane = threadIdx.x & 31;
    if (warp >= MW) return;
    int bi  = warp / (NWIN*NTOK);
    int rem = warp - bi*(NWIN*NTOK);
    int w = rem / NTOK, n = rem - w*NTOK;
    int r = w/9, c = w - r*9, i = n/7, j = n - i*7;
    int hs = r*7 + i + SSZ; if (hs >= HP) hs -= HP;
    int ws = c*7 + j + SSZ; if (ws >= HP) ws -= HP;

    __half2* dst = (__half2*)(g_xh + (size_t)warp*DIM);
    if (hs >= HH || ws >= WW) {
        __half2 z = __floats2half2_rn(0.f, 0.f);
        dst[lane*2] = z; dst[lane*2+1] = z;
        dst[64+lane*2] = z; dst[64+lane*2+1] = z;
        return;
    }
    const float4* src = (const float4*)(x + ((size_t)bi*(HH*WW) + hs*WW + ws)*DIM);
    float4 v0 = src[lane], v1 = src[lane+32];
    float s  = v0.x+v0.y+v0.z+v0.w + v1.x+v1.y+v1.z+v1.w;
    float ss = v0.x*v0.x+v0.y*v0.y+v0.z*v0.z+v0.w*v0.w
             + v1.x*v1.x+v1.y*v1.y+v1.z*v1.z+v1.w*v1.w;
    s  = warp_sum(s);
    ss = warp_sum(ss);
    float mu   = s * (1.f/DIM);
    float var  = ss * (1.f/DIM) - mu*mu;
    float rstd = rsqrtf(var + 1e-5f);
    const float4* gv = (const float4*)g;
    const float4* bv = (const float4*)b;
    float4 g0 = gv[lane], g1 = gv[lane+32], b0 = bv[lane], b1 = bv[lane+32];
    dst[lane*2]      = __floats2half2_rn((v0.x-mu)*rstd*g0.x + b0.x, (v0.y-mu)*rstd*g0.y + b0.y);
    dst[lane*2+1]    = __floats2half2_rn((v0.z-mu)*rstd*g0.z + b0.z, (v0.w-mu)*rstd*g0.w + b0.w);
    dst[64+lane*2]   = __floats2half2_rn((v1.x-mu)*rstd*g1.x + b1.x, (v1.y-mu)*rstd*g1.y + b1.y);
    dst[64+lane*2+1] = __floats2half2_rn((v1.z-mu)*rstd*g1.z + b1.z, (v1.w-mu)*rstd*g1.w + b1.w);
}

// ---------------- window reverse + unshift + residual + LN2 (fused) ----------------
__global__ __launch_bounds__(256) void resid_ln2_kernel(
    const float* __restrict__ x, const float* __restrict__ g, const float* __restrict__ b)
{
    int warp = (blockIdx.x * blockDim.x + threadIdx.x) >> 5;
    int lane = threadIdx.x & 31;
    if (warp >= MT) return;
    int bi = warp / (HH*WW), l = warp - bi*(HH*WW);
    int hh = l / WW, ww = l - hh*WW;
    int hs = hh + (HP - SSZ); if (hs >= HP) hs -= HP;
    int ws = ww + (HP - SSZ); if (ws >= HP) ws -= HP;
    int r = hs/7, i = hs - r*7, c = ws/7, j = ws - c*7;
    size_t m = ((size_t)bi*NWIN + r*9 + c)*NTOK + i*7 + j;

    const float4* xs = (const float4*)(x + (size_t)warp*DIM);
    const __half2* ps = (const __half2*)(g_projh + m*DIM);
    float4 a0 = xs[lane], a1 = xs[lane+32];
    __half2 h0 = ps[lane*2], h1 = ps[lane*2+1], h2 = ps[64+lane*2], h3 = ps[64+lane*2+1];
    float2 f0 = __half22float2(h0), f1 = __half22float2(h1);
    float2 f2 = __half22float2(h2), f3 = __half22float2(h3);
    a0.x += f0.x; a0.y += f0.y; a0.z += f1.x; a0.w += f1.y;
    a1.x += f2.x; a1.y += f2.y; a1.z += f3.x; a1.w += f3.y;
    float4* x1 = (float4*)(g_x1 + (size_t)warp*DIM);
    x1[lane] = a0; x1[lane+32] = a1;

    float s  = a0.x+a0.y+a0.z+a0.w + a1.x+a1.y+a1.z+a1.w;
    float ss = a0.x*a0.x+a0.y*a0.y+a0.z*a0.z+a0.w*a0.w
             + a1.x*a1.x+a1.y*a1.y+a1.z*a1.z+a1.w*a1.w;
    s  = warp_sum(s);
    ss = warp_sum(ss);
    float mu   = s * (1.f/DIM);
    float var  = ss * (1.f/DIM) - mu*mu;
    float rstd = rsqrtf(var + 1e-5f);
    const float4* gv = (const float4*)g;
    const float4* bv = (const float4*)b;
    float4 g0 = gv[lane], g1 = gv[lane+32], b0 = bv[lane], b1 = bv[lane+32];
    __half2* dst = (__half2*)(g_yh + (size_t)warp*DIM);
    dst[lane*2]      = __floats2half2_rn((a0.x-mu)*rstd*g0.x + b0.x, (a0.y-mu)*rstd*g0.y + b0.y);
    dst[lane*2+1]    = __floats2half2_rn((a0.z-mu)*rstd*g0.z + b0.z, (a0.w-mu)*rstd*g0.w + b0.w);
    dst[64+lane*2]   = __floats2half2_rn((a1.x-mu)*rstd*g1.x + b1.x, (a1.y-mu)*rstd*g1.y + b1.y);
    dst[64+lane*2+1] = __floats2half2_rn((a1.z-mu)*rstd*g1.z + b1.z, (a1.w-mu)*rstd*g1.w + b1.w);
}

// ---------------- fp16 mma.sync GEMM, BK=64, 3-stage cp.async + ldmatrix ----------------
template<int EPI, typename TOUT>
__global__ __launch_bounds__(256, 2) void hgemm(
    const __half* __restrict__ A, const __half* __restrict__ B,
    const float* __restrict__ bias, const float* __restrict__ Res,
    TOUT* __restrict__ C, int M, int N, int K)
{
    extern __shared__ __half sm[];
    const int tid = threadIdx.x;
    const int m0 = blockIdx.y * BM, n0 = blockIdx.x * BN;
    const int lane = tid & 31, warp = tid >> 5;
    const int wm = (warp >> 1) * 32;     // 4 warps along M
    const int wn = (warp & 1) * 64;      // 2 warps along N
    const int g = lane >> 2, t = lane & 3;
    const int lr = lane & 15, lc = lane >> 4;

    float acc[2][8][4];
    #pragma unroll
    for (int mi = 0; mi < 2; mi++)
        #pragma unroll
        for (int ni = 0; ni < 8; ni++)
            #pragma unroll
            for (int q = 0; q < 4; q++) acc[mi][ni][q] = 0.f;

    const uint32_t sbase = smem_u32(sm);

    auto issue = [&](int kc, int s){
        const int k0 = kc * BK;
        #pragma unroll
        for (int i = 0; i < 4; i++){
            int f = tid + i*256;
            int row = f >> 3, q = f & 7;
            int gr = m0 + row;
            int cl = gr < M ? gr : (M - 1);
            const __half* src = A + (size_t)cl*K + k0 + q*8;
            cp16(sbase + (uint32_t)((s*STGH + row*AH + q*8)*2), src, gr < M ? 16 : 0);
        }
        #pragma unroll
        for (int i = 0; i < 4; i++){
            int f = tid + i*256;
            int row = f >> 4, q = f & 15;
            const __half* src = B + (size_t)(k0 + row)*N + n0 + q*8;
            cp16(sbase + (uint32_t)((s*STGH + BM*AH + row*BH + q*8)*2), src, 16);
        }
        asm volatile("cp.async.commit_group;" ::: "memory");
    };

    const int nch = K / BK;
    issue(0, 0);
    if (nch > 1) issue(1, 1);
    int s = 0;
    for (int kc = 0; kc < nch; kc++){
        if (kc + 1 < nch){
            asm volatile("cp.async.wait_group 1;" ::: "memory");
        } else {
            asm volatile("cp.async.wait_group 0;" ::: "memory");
        }
        __syncthreads();
        if (kc + 2 < nch){
            int s2 = s + 2; if (s2 >= NSTAGE) s2 -= NSTAGE;
            issue(kc + 2, s2);
        }
        const uint32_t sa = sbase + (uint32_t)(s*STGH)*2;
        const uint32_t sb = sbase + (uint32_t)(s*STGH + BM*AH)*2;
        #pragma unroll
        for (int kk = 0; kk < 4; kk++){
            uint32_t af[2][4];
            #pragma unroll
            for (int mi = 0; mi < 2; mi++)
                ldsm4(af[mi], sa + (uint32_t)(((wm + mi*16 + lr)*AH + kk*16 + lc*8)*2));
            #pragma unroll
            for (int nb = 0; nb < 4; nb++){
                uint32_t bf[4];
                ldsm4t(bf, sb + (uint32_t)(((kk*16 + lr)*BH + wn + nb*16 + lc*8)*2));
                mma16816(acc[0][nb*2+0], af[0], bf[0], bf[1]);
                mma16816(acc[1][nb*2+0], af[1], bf[0], bf[1]);
                mma16816(acc[0][nb*2+1], af[0], bf[2], bf[3]);
                mma16816(acc[1][nb*2+1], af[1], bf[2], bf[3]);
            }
        }
        if (++s >= NSTAGE) s = 0;
    }

    #pragma unroll
    for (int mi = 0; mi < 2; mi++){
        const int r0 = m0 + wm + mi*16 + g;
        #pragma unroll
        for (int half = 0; half < 2; half++){
            const int gr = r0 + half*8;
            if (gr < M){
                #pragma unroll
                for (int ni = 0; ni < 8; ni++){
                    const int col = n0 + wn + ni*8 + t*2;
                    float2 bb = *(const float2*)(bias + col);
                    float v0 = acc[mi][ni][half*2 + 0] + bb.x;
                    float v1 = acc[mi][ni][half*2 + 1] + bb.y;
                    if (EPI == 1){
                        v0 = 0.5f*v0*(1.f + erff(v0*0.70710678118654752f));
                        v1 = 0.5f*v1*(1.f + erff(v1*0.70710678118654752f));
                    }
                    if (EPI == 2){
                        float2 rr = *(const float2*)(Res + (size_t)gr*N + col);
                        v0 += rr.x; v1 += rr.y;
                    }
                    if (sizeof(TOUT) == 2){
                        *(__half2*)((__half*)C + (size_t)gr*N + col) = __floats2half2_rn(v0, v1);
                    } else {
                        *(float2*)((float*)C + (size_t)gr*N + col) = make_float2(v0, v1);
                    }
                }
            }
        }
    }
}

// ---------------- attention: fp16 MMA + table bias + register softmax ----------------
#define QH 40   // Q/K/V smem row stride (halves) — LDSM conflict-free
#define PH 72   // P smem row stride (halves)     — LDSM conflict-free
__global__ __launch_bounds__(128) void attn_kernel()
{
    __shared__ __half Qs[64][QH];
    __shared__ __half Ks[64][QH];
    __shared__ __half Vs[64][QH];
    __shared__ __half Ps[64][PH];

    const int tid = threadIdx.x;
    const int warp = tid >> 5, lane = tid & 31;
    const int g = lane >> 2, t = lane & 3;
    const int lr = lane & 15, lc = lane >> 4;
    const int wh  = blockIdx.x;
    const int win = wh >> 3;
    const int h   = wh & 7;

    // ---- load q,k,v (fp16) into smem; pad rows zeroed
    const __half* base = g_qkvh + (size_t)win*NTOK*(3*DIM) + h*HD;
    for (int e = tid; e < 64*16; e += 128){
        int n = e >> 4, d = e & 15;
        __half2 q, k, v;
        if (n < NTOK){
            const __half2* row = (const __half2*)(base + (size_t)n*(3*DIM));
            q = row[d]; k = row[(DIM>>1) + d]; v = row[DIM + d];
        } else {
            q = __floats2half2_rn(0.f,0.f); k = q; v = q;
        }
        *(__half2*)&Qs[n][d*2] = q;
        *(__half2*)&Ks[n][d*2] = k;
        *(__half2*)&Vs[n][d*2] = v;
    }
    __syncthreads();

    // ---- S = Q @ K^T
    float accs[8][4];
    #pragma unroll
    for (int ni = 0; ni < 8; ni++)
        #pragma unroll
        for (int q = 0; q < 4; q++) accs[ni][q] = 0.f;

    const uint32_t qb = smem_u32(Qs), kb = smem_u32(Ks);
    #pragma unroll
    for (int kk = 0; kk < 2; kk++){
        uint32_t a[4];
        ldsm4(a, qb + (uint32_t)(((16*warp + lr)*QH + kk*16 + lc*8)*2));
        #pragma unroll
        for (int nb = 0; nb < 4; nb++){
            uint32_t b[4];
            ldsm4(b, kb + (uint32_t)(((nb*16 + lr)*QH + kk*16 + lc*8)*2));
            mma16816(accs[nb*2+0], a, b[0], b[2]);
            mma16816(accs[nb*2+1], a, b[1], b[3]);
        }
    }

    // ---- bias table variant for this window
    const int w  = win % NWIN;
    const int wr = w / 9, wc = w - (w/9)*9;
    const int variant = (wr == 8 ? 1 : 0) | (wc == 8 ? 2 : 0);
    const float* tab = g_bias + (size_t)(variant*NHEAD + h)*64*64;
    const float scale = 0.17677669529663687f;   // 1/sqrt(32)

    // ---- epilogue + register softmax: each row is held by 4 lanes (same g, t=0..3)
    #pragma unroll
    for (int half = 0; half < 2; half++){
        const int row = 16*warp + half*8 + g;
        const float* trow = tab + row*64;
        float mx = -1e30f;
        #pragma unroll
        for (int ni = 0; ni < 8; ni++){
            int col = ni*8 + t*2;
            float2 bb = *(const float2*)(trow + col);
            float v0 = fmaf(accs[ni][half*2 + 0], scale, bb.x);
            float v1 = fmaf(accs[ni][half*2 + 1], scale, bb.y);
            accs[ni][half*2 + 0] = v0;
            accs[ni][half*2 + 1] = v1;
            mx = fmaxf(mx, fmaxf(v0, v1));
        }
        mx = fmaxf(mx, __shfl_xor_sync(0xffffffffu, mx, 1));
        mx = fmaxf(mx, __shfl_xor_sync(0xffffffffu, mx, 2));
        float sum = 0.f;
        #pragma unroll
        for (int ni = 0; ni < 8; ni++){
            float e0 = __expf(accs[ni][half*2 + 0] - mx);
            float e1 = __expf(accs[ni][half*2 + 1] - mx);
            accs[ni][half*2 + 0] = e0;
            accs[ni][half*2 + 1] = e1;
            sum += e0 + e1;
        }
        sum += __shfl_xor_sync(0xffffffffu, sum, 1);
        sum += __shfl_xor_sync(0xffffffffu, sum, 2);
        float inv = 1.f / sum;
        #pragma unroll
        for (int ni = 0; ni < 8; ni++){
            int col = ni*8 + t*2;
            *(__half2*)&Ps[row][col] = __floats2half2_rn(
                accs[ni][half*2 + 0]*inv, accs[ni][half*2 + 1]*inv);
        }
    }
    __syncthreads();

    // ---- O = P @ V
    float acco[4][4];
    #pragma unroll
    for (int ni = 0; ni < 4; ni++)
        #pragma unroll
        for (int q = 0; q < 4; q++) acco[ni][q] = 0.f;

    const uint32_t pb = smem_u32(Ps), vb = smem_u32(Vs);
    #pragma unroll
    for (int kk = 0; kk < 4; kk++){
        uint32_t a[4];
        ldsm4(a, pb + (uint32_t)(((16*warp + lr)*PH + kk*16 + lc*8)*2));
        #pragma unroll
        for (int nb = 0; nb < 2; nb++){
            uint32_t b[4];
            ldsm4t(b, vb + (uint32_t)(((kk*16 + lr)*QH + nb*16 + lc*8)*2));
            mma16816(acco[nb*2+0], a, b[0], b[1]);
            mma16816(acco[nb*2+1], a, b[2], b[3]);
        }
    }

    // ---- write O (fp16)
    __half* out = g_atth + (size_t)win*NTOK*DIM + h*HD;
    #pragma unroll
    for (int ni = 0; ni < 4; ni++){
        #pragma unroll
        for (int half = 0; half < 2; half++){
            int row = 16*warp + half*8 + g;
            if (row < NTOK){
                int col = ni*8 + t*2;
                *(__half2*)(out + (size_t)row*DIM + col) =
                    __floats2half2_rn(acco[ni][half*2 + 0], acco[ni][half*2 + 1]);
            }
        }
    }
}

// ---------------- host launcher ----------------
extern "C" void kernel_launch(void* const* d_in, const int* in_sizes, int n_in,
                              void* d_out, int out_size)
{
    (void)in_sizes; (void)n_in; (void)out_size;
    const float* x      = (const float*)d_in[0];
    const float* g1     = (const float*)d_in[1];
    const float* b1     = (const float*)d_in[2];
    const float* w_qkv  = (const float*)d_in[3];
    const float* b_qkv  = (const float*)d_in[4];
    const float* relt   = (const float*)d_in[5];
    const float* w_proj = (const float*)d_in[6];
    const float* b_proj = (const float*)d_in[7];
    const float* g2     = (const float*)d_in[8];
    const float* b2     = (const float*)d_in[9];
    const float* w_fc1  = (const float*)d_in[10];
    const float* b_fc1  = (const float*)d_in[11];
    const float* w_fc2  = (const float*)d_in[12];
    const float* b_fc2  = (const float*)d_in[13];
    float* out = (float*)d_out;

    __half *p_xh, *p_qkvh, *p_atth, *p_projh, *p_yh, *p_hh, *p_wq, *p_wp, *p_w1, *p_w2;
    float *p_x1;
    cudaGetSymbolAddress((void**)&p_xh,  g_xh);
    cudaGetSymbolAddress((void**)&p_qkvh,g_qkvh);
    cudaGetSymbolAddress((void**)&p_atth,g_atth);
    cudaGetSymbolAddress((void**)&p_projh,g_projh);
    cudaGetSymbolAddress((void**)&p_x1,  g_x1);
    cudaGetSymbolAddress((void**)&p_yh,  g_yh);
    cudaGetSymbolAddress((void**)&p_hh,  g_hh);
    cudaGetSymbolAddress((void**)&p_wq,  g_wq);
    cudaGetSymbolAddress((void**)&p_wp,  g_wp);
    cudaGetSymbolAddress((void**)&p_w1,  g_w1);
    cudaGetSymbolAddress((void**)&p_w2,  g_w2);

    cudaFuncSetAttribute(hgemm<0,__half>, cudaFuncAttributeMaxDynamicSharedMemorySize, GEMM_SMEM);
    cudaFuncSetAttribute(hgemm<1,__half>, cudaFuncAttributeMaxDynamicSharedMemorySize, GEMM_SMEM);
    cudaFuncSetAttribute(hgemm<2,float>,  cudaFuncAttributeMaxDynamicSharedMemorySize, GEMM_SMEM);

    // 0) weights -> fp16; attention bias table
    f2h_all<<<(393216 + 255)/256, 256>>>(w_qkv, w_proj, w_fc1, w_fc2, p_wq, p_wp, p_w1, p_w2);
    bias_table_kernel<<<4*NHEAD, 128>>>(relt);

    // 1) LN1 + pad + shift + window partition (fp16)
    ln1_window_kernel<<<(MW*32 + 255)/256, 256>>>(x, g1, b1);

    // 2) QKV GEMM [MW,256]x[256,768] -> fp16
    hgemm<0,__half><<<dim3(768/BN, (MW + BM - 1)/BM), 256, GEMM_SMEM>>>(
        p_xh, p_wq, b_qkv, (const float*)0, p_qkvh, MW, 768, 256);

    // 3) attention (fp16 MMA, table bias, register softmax) -> fp16
    attn_kernel<<<BATCH*NWIN*NHEAD, 128>>>();

    // 4) proj GEMM [MW,256]x[256,256] -> fp16
    hgemm<0,__half><<<dim3(256/BN, (MW + BM - 1)/BM), 256, GEMM_SMEM>>>(
        p_atth, p_wp, b_proj, (const float*)0, p_projh, MW, 256, 256);

    // 5) window reverse + unshift + residual + LN2
    resid_ln2_kernel<<<(MT*32 + 255)/256, 256>>>(x, g2, b2);

    // 6) fc1 + GELU [MT,256]x[256,1024] -> fp16
    hgemm<1,__half><<<dim3(1024/BN, MT/BM), 256, GEMM_SMEM>>>(
        p_yh, p_w1, b_fc1, (const float*)0, p_hh, MT, 1024, 256);

    // 7) fc2 + bias + residual [MT,1024]x[1024,256] -> out fp32
    hgemm<2,float><<<dim3(256/BN, MT/BM), 256, GEMM_SMEM>>>(
        p_hh, p_w2, b_fc2, p_x1, out, MT, 256, 1024);
}

// round 15
// speedup vs baseline: 1.1224x; 1.0103x over previous
#include <cuda_runtime.h>
#include <cuda_fp16.h>
#include <math.h>
#include <stdint.h>

// ---------------- static config ----------------
#define BATCH 24
#define HH 60
#define WW 60
#define HP 63
#define WSZ 7
#define SSZ 3
#define NWIN 81          // 9x9 windows
#define NTOK 49          // tokens per window
#define DIM 256
#define NHEAD 8
#define HD 32
#define MW (BATCH*NWIN*NTOK)   // 95256 window tokens
#define MT (BATCH*HH*WW)       // 86400 real tokens

// GEMM tiling (mma.sync m16n8k16 fp16)
#define BM 128
#define BN 128
#define BK 64
#define AH 72                  // A smem row stride (halves) — LDSM conflict-free
#define BH 136                 // B smem row stride (halves) — LDSM.T conflict-free
#define STGH (BM*AH + BK*BH)   // halves per stage = 9216 + 8704 = 17920
#define NSTAGE 3
#define GEMM_SMEM (NSTAGE*STGH*2)   // 107520 bytes

// ---------------- scratch (static device globals) ----------------
__device__ __half g_xh  [(size_t)MW*DIM];     // LN1 windowed output (fp16)
__device__ __half g_qkvh[(size_t)MW*3*DIM];   // qkv (fp16)
__device__ __half g_atth[(size_t)MW*DIM];     // attention output (fp16)
__device__ __half g_projh[(size_t)MW*DIM];    // proj output (fp16, window layout)
__device__ float  g_x1  [(size_t)MT*DIM];     // x + attn branch (fp32)
__device__ __half g_yh  [(size_t)MT*DIM];     // LN2 output (fp16)
__device__ __half g_hh  [(size_t)MT*4*DIM];   // fc1 output (fp16)
// fp16 weights
__device__ __half g_wq[256*768];
__device__ __half g_wp[256*256];
__device__ __half g_w1[256*1024];
__device__ __half g_w2[1024*256];
// precomputed attention bias+mask table: [variant][head][64][64] fp32
__device__ float g_bias[4*NHEAD*64*64];

// ---------------- helpers ----------------
__device__ __forceinline__ uint32_t smem_u32(const void* p){
    return (uint32_t)__cvta_generic_to_shared((void*)p);
}
__device__ __forceinline__ void ldsm4(uint32_t* r, uint32_t addr){
    asm volatile("ldmatrix.sync.aligned.m8n8.x4.shared.b16 {%0,%1,%2,%3}, [%4];"
        : "=r"(r[0]),"=r"(r[1]),"=r"(r[2]),"=r"(r[3]) : "r"(addr));
}
__device__ __forceinline__ void ldsm4t(uint32_t* r, uint32_t addr){
    asm volatile("ldmatrix.sync.aligned.m8n8.x4.trans.shared.b16 {%0,%1,%2,%3}, [%4];"
        : "=r"(r[0]),"=r"(r[1]),"=r"(r[2]),"=r"(r[3]) : "r"(addr));
}
__device__ __forceinline__ void mma16816(float* c, const uint32_t* a, uint32_t b0, uint32_t b1){
    asm volatile("mma.sync.aligned.m16n8k16.row.col.f32.f16.f16.f32 "
        "{%0,%1,%2,%3}, {%4,%5,%6,%7}, {%8,%9}, {%0,%1,%2,%3};"
        : "+f"(c[0]),"+f"(c[1]),"+f"(c[2]),"+f"(c[3])
        : "r"(a[0]),"r"(a[1]),"r"(a[2]),"r"(a[3]), "r"(b0),"r"(b1));
}
__device__ __forceinline__ void cp16(uint32_t saddr, const void* g, int sz){
    asm volatile("cp.async.cg.shared.global [%0], [%1], 16, %2;"
                 :: "r"(saddr), "l"(g), "r"(sz) : "memory");
}
__device__ __forceinline__ float warp_sum(float v){
    #pragma unroll
    for (int o = 16; o; o >>= 1) v += __shfl_xor_sync(0xffffffffu, v, o);
    return v;
}

// ---------------- fused fp32 -> fp16 weight conversion (all 4 weights) ----------------
__global__ void f2h_all(const float* __restrict__ s0, const float* __restrict__ s1,
                        const float* __restrict__ s2, const float* __restrict__ s3,
                        __half* __restrict__ d0, __half* __restrict__ d1,
                        __half* __restrict__ d2, __half* __restrict__ d3)
{
    int i = blockIdx.x*blockDim.x + threadIdx.x;
    if (i >= 393216) return;
    const float* s; __half* d; int off;
    if (i < 98304)        { s = s0; d = d0; off = i; }
    else if (i < 131072)  { s = s1; d = d1; off = i - 98304; }
    else if (i < 262144)  { s = s2; d = d2; off = i - 131072; }
    else                  { s = s3; d = d3; off = i - 262144; }
    float2 v = ((const float2*)s)[off];
    ((__half2*)d)[off] = __floats2half2_rn(v.x, v.y);
}

// ---------------- bias+mask table precompute: [variant][head][64][64] ----------------
__global__ void bias_table_kernel(const float* __restrict__ relt)
{
    int v = blockIdx.x >> 3, h = blockIdx.x & 7;
    bool rm = (v & 1) != 0, cm = (v & 2) != 0;
    float* dst = g_bias + (size_t)(v*NHEAD + h)*64*64;
    for (int e = threadIdx.x; e < 64*64; e += 128){
        int n = e >> 6, m = e & 63;
        float val;
        if (m >= NTOK){
            val = -20000.f;                 // pad col: exp -> 0
        } else {
            int nn = n < NTOK ? n : NTOK - 1;
            int in_ = nn/7, jn = nn - in_*7;
            int im  = m/7,  jm = m  - im*7;
            val = relt[((in_ - im + 6)*13 + (jn - jm + 6))*NHEAD + h];
            int rn = (rm ? (in_ < 4 ? 1 : 2) : 0)*3 + (cm ? (jn < 4 ? 1 : 2) : 0);
            int rmm= (rm ? (im  < 4 ? 1 : 2) : 0)*3 + (cm ? (jm  < 4 ? 1 : 2) : 0);
            if (rn != rmm) val -= 100.f;
        }
        dst[e] = val;
    }
}

// ---------------- LN1 + pad + shift + window partition (fp16 out) ----------------
__global__ __launch_bounds__(256) void ln1_window_kernel(
    const float* __restrict__ x, const float* __restrict__ g, const float* __restrict__ b)
{
    int warp = (blockIdx.x * blockDim.x + threadIdx.x) >> 5;
    int lane = threadIdx.x & 31;
    if (warp >= MW) return;
    int bi  = warp / (NWIN*NTOK);
    int rem = warp - bi*(NWIN*NTOK);
    int w = rem / NTOK, n = rem - w*NTOK;
    int r = w/9, c = w - r*9, i = n/7, j = n - i*7;
    int hs = r*7 + i + SSZ; if (hs >= HP) hs -= HP;
    int ws = c*7 + j + SSZ; if (ws >= HP) ws -= HP;

    __half2* dst = (__half2*)(g_xh + (size_t)warp*DIM);
    if (hs >= HH || ws >= WW) {
        __half2 z = __floats2half2_rn(0.f, 0.f);
        dst[lane*2] = z; dst[lane*2+1] = z;
        dst[64+lane*2] = z; dst[64+lane*2+1] = z;
        return;
    }
    const float4* src = (const float4*)(x + ((size_t)bi*(HH*WW) + hs*WW + ws)*DIM);
    float4 v0 = src[lane], v1 = src[lane+32];
    float s  = v0.x+v0.y+v0.z+v0.w + v1.x+v1.y+v1.z+v1.w;
    float ss = v0.x*v0.x+v0.y*v0.y+v0.z*v0.z+v0.w*v0.w
             + v1.x*v1.x+v1.y*v1.y+v1.z*v1.z+v1.w*v1.w;
    s  = warp_sum(s);
    ss = warp_sum(ss);
    float mu   = s * (1.f/DIM);
    float var  = ss * (1.f/DIM) - mu*mu;
    float rstd = rsqrtf(var + 1e-5f);
    const float4* gv = (const float4*)g;
    const float4* bv = (const float4*)b;
    float4 g0 = gv[lane], g1 = gv[lane+32], b0 = bv[lane], b1 = bv[lane+32];
    dst[lane*2]      = __floats2half2_rn((v0.x-mu)*rstd*g0.x + b0.x, (v0.y-mu)*rstd*g0.y + b0.y);
    dst[lane*2+1]    = __floats2half2_rn((v0.z-mu)*rstd*g0.z + b0.z, (v0.w-mu)*rstd*g0.w + b0.w);
    dst[64+lane*2]   = __floats2half2_rn((v1.x-mu)*rstd*g1.x + b1.x, (v1.y-mu)*rstd*g1.y + b1.y);
    dst[64+lane*2+1] = __floats2half2_rn((v1.z-mu)*rstd*g1.z + b1.z, (v1.w-mu)*rstd*g1.w + b1.w);
}

// ---------------- window reverse + unshift + residual + LN2 (fused) ----------------
__global__ __launch_bounds__(256) void resid_ln2_kernel(
    const float* __restrict__ x, const float* __restrict__ g, const float* __restrict__ b)
{
    int warp = (blockIdx.x * blockDim.x + threadIdx.x) >> 5;
    int lane = threadIdx.x & 31;
    if (warp >= MT) return;
    int bi = warp / (HH*WW), l = warp - bi*(HH*WW);
    int hh = l / WW, ww = l - hh*WW;
    int hs = hh + (HP - SSZ); if (hs >= HP) hs -= HP;
    int ws = ww + (HP - SSZ); if (ws >= HP) ws -= HP;
    int r = hs/7, i = hs - r*7, c = ws/7, j = ws - c*7;
    size_t m = ((size_t)bi*NWIN + r*9 + c)*NTOK + i*7 + j;

    const float4* xs = (const float4*)(x + (size_t)warp*DIM);
    const __half2* ps = (const __half2*)(g_projh + m*DIM);
    float4 a0 = xs[lane], a1 = xs[lane+32];
    __half2 h0 = ps[lane*2], h1 = ps[lane*2+1], h2 = ps[64+lane*2], h3 = ps[64+lane*2+1];
    float2 f0 = __half22float2(h0), f1 = __half22float2(h1);
    float2 f2 = __half22float2(h2), f3 = __half22float2(h3);
    a0.x += f0.x; a0.y += f0.y; a0.z += f1.x; a0.w += f1.y;
    a1.x += f2.x; a1.y += f2.y; a1.z += f3.x; a1.w += f3.y;
    float4* x1 = (float4*)(g_x1 + (size_t)warp*DIM);
    x1[lane] = a0; x1[lane+32] = a1;

    float s  = a0.x+a0.y+a0.z+a0.w + a1.x+a1.y+a1.z+a1.w;
    float ss = a0.x*a0.x+a0.y*a0.y+a0.z*a0.z+a0.w*a0.w
             + a1.x*a1.x+a1.y*a1.y+a1.z*a1.z+a1.w*a1.w;
    s  = warp_sum(s);
    ss = warp_sum(ss);
    float mu   = s * (1.f/DIM);
    float var  = ss * (1.f/DIM) - mu*mu;
    float rstd = rsqrtf(var + 1e-5f);
    const float4* gv = (const float4*)g;
    const float4* bv = (const float4*)b;
    float4 g0 = gv[lane], g1 = gv[lane+32], b0 = bv[lane], b1 = bv[lane+32];
    __half2* dst = (__half2*)(g_yh + (size_t)warp*DIM);
    dst[lane*2]      = __floats2half2_rn((a0.x-mu)*rstd*g0.x + b0.x, (a0.y-mu)*rstd*g0.y + b0.y);
    dst[lane*2+1]    = __floats2half2_rn((a0.z-mu)*rstd*g0.z + b0.z, (a0.w-mu)*rstd*g0.w + b0.w);
    dst[64+lane*2]   = __floats2half2_rn((a1.x-mu)*rstd*g1.x + b1.x, (a1.y-mu)*rstd*g1.y + b1.y);
    dst[64+lane*2+1] = __floats2half2_rn((a1.z-mu)*rstd*g1.z + b1.z, (a1.w-mu)*rstd*g1.w + b1.w);
}

// ---------------- fp16 mma.sync GEMM, BK=64, 3-stage cp.async + batched ldmatrix ----------------
template<int EPI, typename TOUT>
__global__ __launch_bounds__(256, 2) void hgemm(
    const __half* __restrict__ A, const __half* __restrict__ B,
    const float* __restrict__ bias, const float* __restrict__ Res,
    TOUT* __restrict__ C, int M, int N, int K)
{
    extern __shared__ __half sm[];
    const int tid = threadIdx.x;
    const int m0 = blockIdx.y * BM, n0 = blockIdx.x * BN;
    const int lane = tid & 31, warp = tid >> 5;
    const int wm = (warp >> 1) * 32;     // 4 warps along M
    const int wn = (warp & 1) * 64;      // 2 warps along N
    const int g = lane >> 2, t = lane & 3;
    const int lr = lane & 15, lc = lane >> 4;

    float acc[2][8][4];
    #pragma unroll
    for (int mi = 0; mi < 2; mi++)
        #pragma unroll
        for (int ni = 0; ni < 8; ni++)
            #pragma unroll
            for (int q = 0; q < 4; q++) acc[mi][ni][q] = 0.f;

    const uint32_t sbase = smem_u32(sm);

    auto issue = [&](int kc, int s){
        const int k0 = kc * BK;
        #pragma unroll
        for (int i = 0; i < 4; i++){
            int f = tid + i*256;
            int row = f >> 3, q = f & 7;
            int gr = m0 + row;
            int cl = gr < M ? gr : (M - 1);
            const __half* src = A + (size_t)cl*K + k0 + q*8;
            cp16(sbase + (uint32_t)((s*STGH + row*AH + q*8)*2), src, gr < M ? 16 : 0);
        }
        #pragma unroll
        for (int i = 0; i < 4; i++){
            int f = tid + i*256;
            int row = f >> 4, q = f & 15;
            const __half* src = B + (size_t)(k0 + row)*N + n0 + q*8;
            cp16(sbase + (uint32_t)((s*STGH + BM*AH + row*BH + q*8)*2), src, 16);
        }
        asm volatile("cp.async.commit_group;" ::: "memory");
    };

    const int nch = K / BK;
    issue(0, 0);
    if (nch > 1) issue(1, 1);
    int s = 0;
    for (int kc = 0; kc < nch; kc++){
        if (kc + 1 < nch){
            asm volatile("cp.async.wait_group 1;" ::: "memory");
        } else {
            asm volatile("cp.async.wait_group 0;" ::: "memory");
        }
        __syncthreads();
        if (kc + 2 < nch){
            int s2 = s + 2; if (s2 >= NSTAGE) s2 -= NSTAGE;
            issue(kc + 2, s2);
        }
        const uint32_t sa = sbase + (uint32_t)(s*STGH)*2;
        const uint32_t sb = sbase + (uint32_t)(s*STGH + BM*AH)*2;
        #pragma unroll
        for (int kk = 0; kk < 4; kk++){
            // batched fragment loads: 6 LDSM issued back-to-back, then 16 MMAs
            uint32_t af[2][4];
            uint32_t bf[4][4];
            #pragma unroll
            for (int mi = 0; mi < 2; mi++)
                ldsm4(af[mi], sa + (uint32_t)(((wm + mi*16 + lr)*AH + kk*16 + lc*8)*2));
            #pragma unroll
            for (int nb = 0; nb < 4; nb++)
                ldsm4t(bf[nb], sb + (uint32_t)(((kk*16 + lr)*BH + wn + nb*16 + lc*8)*2));
            #pragma unroll
            for (int nb = 0; nb < 4; nb++){
                mma16816(acc[0][nb*2+0], af[0], bf[nb][0], bf[nb][1]);
                mma16816(acc[1][nb*2+0], af[1], bf[nb][0], bf[nb][1]);
                mma16816(acc[0][nb*2+1], af[0], bf[nb][2], bf[nb][3]);
                mma16816(acc[1][nb*2+1], af[1], bf[nb][2], bf[nb][3]);
            }
        }
        if (++s >= NSTAGE) s = 0;
    }

    #pragma unroll
    for (int mi = 0; mi < 2; mi++){
        const int r0 = m0 + wm + mi*16 + g;
        #pragma unroll
        for (int half = 0; half < 2; half++){
            const int gr = r0 + half*8;
            if (gr < M){
                #pragma unroll
                for (int ni = 0; ni < 8; ni++){
                    const int col = n0 + wn + ni*8 + t*2;
                    float2 bb = *(const float2*)(bias + col);
                    float v0 = acc[mi][ni][half*2 + 0] + bb.x;
                    float v1 = acc[mi][ni][half*2 + 1] + bb.y;
                    if (EPI == 1){
                        v0 = 0.5f*v0*(1.f + erff(v0*0.70710678118654752f));
                        v1 = 0.5f*v1*(1.f + erff(v1*0.70710678118654752f));
                    }
                    if (EPI == 2){
                        float2 rr = *(const float2*)(Res + (size_t)gr*N + col);
                        v0 += rr.x; v1 += rr.y;
                    }
                    if (sizeof(TOUT) == 2){
                        *(__half2*)((__half*)C + (size_t)gr*N + col) = __floats2half2_rn(v0, v1);
                    } else {
                        *(float2*)((float*)C + (size_t)gr*N + col) = make_float2(v0, v1);
                    }
                }
            }
        }
    }
}

// ---------------- attention: fp16 MMA + table bias + register softmax ----------------
#define QH 40   // Q/K/V smem row stride (halves) — LDSM conflict-free
#define PH 72   // P smem row stride (halves)     — LDSM conflict-free
__global__ __launch_bounds__(128) void attn_kernel()
{
    __shared__ __half Qs[64][QH];
    __shared__ __half Ks[64][QH];
    __shared__ __half Vs[64][QH];
    __shared__ __half Ps[64][PH];

    const int tid = threadIdx.x;
    const int warp = tid >> 5, lane = tid & 31;
    const int g = lane >> 2, t = lane & 3;
    const int lr = lane & 15, lc = lane >> 4;
    const int wh  = blockIdx.x;
    const int win = wh >> 3;
    const int h   = wh & 7;

    const __half* base = g_qkvh + (size_t)win*NTOK*(3*DIM) + h*HD;
    for (int e = tid; e < 64*16; e += 128){
        int n = e >> 4, d = e & 15;
        __half2 q, k, v;
        if (n < NTOK){
            const __half2* row = (const __half2*)(base + (size_t)n*(3*DIM));
            q = row[d]; k = row[(DIM>>1) + d]; v = row[DIM + d];
        } else {
            q = __floats2half2_rn(0.f,0.f); k = q; v = q;
        }
        *(__half2*)&Qs[n][d*2] = q;
        *(__half2*)&Ks[n][d*2] = k;
        *(__half2*)&Vs[n][d*2] = v;
    }
    __syncthreads();

    // ---- S = Q @ K^T (batched LDSM then MMA)
    float accs[8][4];
    #pragma unroll
    for (int ni = 0; ni < 8; ni++)
        #pragma unroll
        for (int q = 0; q < 4; q++) accs[ni][q] = 0.f;

    const uint32_t qb = smem_u32(Qs), kb = smem_u32(Ks);
    #pragma unroll
    for (int kk = 0; kk < 2; kk++){
        uint32_t a[4];
        uint32_t b[4][4];
        ldsm4(a, qb + (uint32_t)(((16*warp + lr)*QH + kk*16 + lc*8)*2));
        #pragma unroll
        for (int nb = 0; nb < 4; nb++)
            ldsm4(b[nb], kb + (uint32_t)(((nb*16 + lr)*QH + kk*16 + lc*8)*2));
        #pragma unroll
        for (int nb = 0; nb < 4; nb++){
            mma16816(accs[nb*2+0], a, b[nb][0], b[nb][2]);
            mma16816(accs[nb*2+1], a, b[nb][1], b[nb][3]);
        }
    }

    // ---- bias table variant for this window
    const int w  = win % NWIN;
    const int wr = w / 9, wc = w - (w/9)*9;
    const int variant = (wr == 8 ? 1 : 0) | (wc == 8 ? 2 : 0);
    const float* tab = g_bias + (size_t)(variant*NHEAD + h)*64*64;
    const float scale = 0.17677669529663687f;   // 1/sqrt(32)

    // ---- epilogue + register softmax
    #pragma unroll
    for (int half = 0; half < 2; half++){
        const int row = 16*warp + half*8 + g;
        const float* trow = tab + row*64;
        float mx = -1e30f;
        #pragma unroll
        for (int ni = 0; ni < 8; ni++){
            int col = ni*8 + t*2;
            float2 bb = *(const float2*)(trow + col);
            float v0 = fmaf(accs[ni][half*2 + 0], scale, bb.x);
            float v1 = fmaf(accs[ni][half*2 + 1], scale, bb.y);
            accs[ni][half*2 + 0] = v0;
            accs[ni][half*2 + 1] = v1;
            mx = fmaxf(mx, fmaxf(v0, v1));
        }
        mx = fmaxf(mx, __shfl_xor_sync(0xffffffffu, mx, 1));
        mx = fmaxf(mx, __shfl_xor_sync(0xffffffffu, mx, 2));
        float sum = 0.f;
        #pragma unroll
        for (int ni = 0; ni < 8; ni++){
            float e0 = __expf(accs[ni][half*2 + 0] - mx);
            float e1 = __expf(accs[ni][half*2 + 1] - mx);
            accs[ni][half*2 + 0] = e0;
            accs[ni][half*2 + 1] = e1;
            sum += e0 + e1;
        }
        sum += __shfl_xor_sync(0xffffffffu, sum, 1);
        sum += __shfl_xor_sync(0xffffffffu, sum, 2);
        float inv = 1.f / sum;
        #pragma unroll
        for (int ni = 0; ni < 8; ni++){
            int col = ni*8 + t*2;
            *(__half2*)&Ps[row][col] = __floats2half2_rn(
                accs[ni][half*2 + 0]*inv, accs[ni][half*2 + 1]*inv);
        }
    }
    __syncthreads();

    // ---- O = P @ V (batched LDSM then MMA)
    float acco[4][4];
    #pragma unroll
    for (int ni = 0; ni < 4; ni++)
        #pragma unroll
        for (int q = 0; q < 4; q++) acco[ni][q] = 0.f;

    const uint32_t pb = smem_u32(Ps), vb = smem_u32(Vs);
    #pragma unroll
    for (int kk = 0; kk < 4; kk++){
        uint32_t a[4];
        uint32_t b[2][4];
        ldsm4(a, pb + (uint32_t)(((16*warp + lr)*PH + kk*16 + lc*8)*2));
        #pragma unroll
        for (int nb = 0; nb < 2; nb++)
            ldsm4t(b[nb], vb + (uint32_t)(((kk*16 + lr)*QH + nb*16 + lc*8)*2));
        #pragma unroll
        for (int nb = 0; nb < 2; nb++){
            mma16816(acco[nb*2+0], a, b[nb][0], b[nb][1]);
            mma16816(acco[nb*2+1], a, b[nb][2], b[nb][3]);
        }
    }

    // ---- write O (fp16)
    __half* out = g_atth + (size_t)win*NTOK*DIM + h*HD;
    #pragma unroll
    for (int ni = 0; ni < 4; ni++){
        #pragma unroll
        for (int half = 0; half < 2; half++){
            int row = 16*warp + half*8 + g;
            if (row < NTOK){
                int col = ni*8 + t*2;
                *(__half2*)(out + (size_t)row*DIM + col) =
                    __floats2half2_rn(acco[ni][half*2 + 0], acco[ni][half*2 + 1]);
            }
        }
    }
}

// ---------------- host launcher ----------------
extern "C" void kernel_launch(void* const* d_in, const int* in_sizes, int n_in,
                              void* d_out, int out_size)
{
    (void)in_sizes; (void)n_in; (void)out_size;
    const float* x      = (const float*)d_in[0];
    const float* g1     = (const float*)d_in[1];
    const float* b1     = (const float*)d_in[2];
    const float* w_qkv  = (const float*)d_in[3];
    const float* b_qkv  = (const float*)d_in[4];
    const float* relt   = (const float*)d_in[5];
    const float* w_proj = (const float*)d_in[6];
    const float* b_proj = (const float*)d_in[7];
    const float* g2     = (const float*)d_in[8];
    const float* b2     = (const float*)d_in[9];
    const float* w_fc1  = (const float*)d_in[10];
    const float* b_fc1  = (const float*)d_in[11];
    const float* w_fc2  = (const float*)d_in[12];
    const float* b_fc2  = (const float*)d_in[13];
    float* out = (float*)d_out;

    __half *p_xh, *p_qkvh, *p_atth, *p_projh, *p_yh, *p_hh, *p_wq, *p_wp, *p_w1, *p_w2;
    float *p_x1;
    cudaGetSymbolAddress((void**)&p_xh,  g_xh);
    cudaGetSymbolAddress((void**)&p_qkvh,g_qkvh);
    cudaGetSymbolAddress((void**)&p_atth,g_atth);
    cudaGetSymbolAddress((void**)&p_projh,g_projh);
    cudaGetSymbolAddress((void**)&p_x1,  g_x1);
    cudaGetSymbolAddress((void**)&p_yh,  g_yh);
    cudaGetSymbolAddress((void**)&p_hh,  g_hh);
    cudaGetSymbolAddress((void**)&p_wq,  g_wq);
    cudaGetSymbolAddress((void**)&p_wp,  g_wp);
    cudaGetSymbolAddress((void**)&p_w1,  g_w1);
    cudaGetSymbolAddress((void**)&p_w2,  g_w2);

    cudaFuncSetAttribute(hgemm<0,__half>, cudaFuncAttributeMaxDynamicSharedMemorySize, GEMM_SMEM);
    cudaFuncSetAttribute(hgemm<1,__half>, cudaFuncAttributeMaxDynamicSharedMemorySize, GEMM_SMEM);
    cudaFuncSetAttribute(hgemm<2,float>,  cudaFuncAttributeMaxDynamicSharedMemorySize, GEMM_SMEM);

    // 0) weights -> fp16; attention bias table
    f2h_all<<<(393216 + 255)/256, 256>>>(w_qkv, w_proj, w_fc1, w_fc2, p_wq, p_wp, p_w1, p_w2);
    bias_table_kernel<<<4*NHEAD, 128>>>(relt);

    // 1) LN1 + pad + shift + window partition (fp16)
    ln1_window_kernel<<<(MW*32 + 255)/256, 256>>>(x, g1, b1);

    // 2) QKV GEMM [MW,256]x[256,768] -> fp16
    hgemm<0,__half><<<dim3(768/BN, (MW + BM - 1)/BM), 256, GEMM_SMEM>>>(
        p_xh, p_wq, b_qkv, (const float*)0, p_qkvh, MW, 768, 256);

    // 3) attention (fp16 MMA, table bias, register softmax) -> fp16
    attn_kernel<<<BATCH*NWIN*NHEAD, 128>>>();

    // 4) proj GEMM [MW,256]x[256,256] -> fp16
    hgemm<0,__half><<<dim3(256/BN, (MW + BM - 1)/BM), 256, GEMM_SMEM>>>(
        p_atth, p_wp, b_proj, (const float*)0, p_projh, MW, 256, 256);

    // 5) window reverse + unshift + residual + LN2
    resid_ln2_kernel<<<(MT*32 + 255)/256, 256>>>(x, g2, b2);

    // 6) fc1 + GELU [MT,256]x[256,1024] -> fp16
    hgemm<1,__half><<<dim3(1024/BN, MT/BM), 256, GEMM_SMEM>>>(
        p_yh, p_w1, b_fc1, (const float*)0, p_hh, MT, 1024, 256);

    // 7) fc2 + bias + residual [MT,1024]x[1024,256] -> out fp32
    hgemm<2,float><<<dim3(256/BN, MT/BM), 256, GEMM_SMEM>>>(
        p_hh, p_w2, b_fc2, p_x1, out, MT, 256, 1024);
}

// round 17
// speedup vs baseline: 1.1239x; 1.0014x over previous
#include <cuda_runtime.h>
#include <cuda_fp16.h>
#include <math.h>
#include <stdint.h>

// ---------------- static config ----------------
#define BATCH 24
#define HH 60
#define WW 60
#define HP 63
#define WSZ 7
#define SSZ 3
#define NWIN 81          // 9x9 windows
#define NTOK 49          // tokens per window
#define DIM 256
#define NHEAD 8
#define HD 32
#define MW (BATCH*NWIN*NTOK)   // 95256 window tokens
#define MT (BATCH*HH*WW)       // 86400 real tokens

// GEMM tiling (mma.sync m16n8k16 fp16)
#define BM 128
#define BN 128
#define BK 64
#define AH 72                  // A smem row stride (halves) — LDSM conflict-free
#define BH 136                 // B smem row stride (halves) — LDSM.T conflict-free
#define STGH (BM*AH + BK*BH)   // halves per stage = 9216 + 8704 = 17920
#define NSTAGE 3
#define GEMM_SMEM (NSTAGE*STGH*2)   // 107520 bytes

// ---------------- scratch (static device globals) ----------------
__device__ __half g_xh  [(size_t)MW*DIM];     // LN1 windowed output (fp16)
__device__ __half g_qkvh[(size_t)MW*3*DIM];   // qkv (fp16)
__device__ __half g_atth[(size_t)MW*DIM];     // attention output (fp16)
__device__ __half g_projh[(size_t)MW*DIM];    // proj output (fp16, window layout)
__device__ float  g_x1  [(size_t)MT*DIM];     // x + attn branch (fp32)
__device__ __half g_yh  [(size_t)MT*DIM];     // LN2 output (fp16)
__device__ __half g_hh  [(size_t)MT*4*DIM];   // fc1 output (fp16)
// fp16 weights
__device__ __half g_wq[256*768];
__device__ __half g_wp[256*256];
__device__ __half g_w1[256*1024];
__device__ __half g_w2[1024*256];
// precomputed attention bias+mask table: [variant][head][64][64] fp32
__device__ float g_bias[4*NHEAD*64*64];

// ---------------- helpers ----------------
__device__ __forceinline__ uint32_t smem_u32(const void* p){
    return (uint32_t)__cvta_generic_to_shared((void*)p);
}
__device__ __forceinline__ void ldsm4(uint32_t* r, uint32_t addr){
    asm volatile("ldmatrix.sync.aligned.m8n8.x4.shared.b16 {%0,%1,%2,%3}, [%4];"
        : "=r"(r[0]),"=r"(r[1]),"=r"(r[2]),"=r"(r[3]) : "r"(addr));
}
__device__ __forceinline__ void ldsm4t(uint32_t* r, uint32_t addr){
    asm volatile("ldmatrix.sync.aligned.m8n8.x4.trans.shared.b16 {%0,%1,%2,%3}, [%4];"
        : "=r"(r[0]),"=r"(r[1]),"=r"(r[2]),"=r"(r[3]) : "r"(addr));
}
__device__ __forceinline__ void mma16816(float* c, const uint32_t* a, uint32_t b0, uint32_t b1){
    asm volatile("mma.sync.aligned.m16n8k16.row.col.f32.f16.f16.f32 "
        "{%0,%1,%2,%3}, {%4,%5,%6,%7}, {%8,%9}, {%0,%1,%2,%3};"
        : "+f"(c[0]),"+f"(c[1]),"+f"(c[2]),"+f"(c[3])
        : "r"(a[0]),"r"(a[1]),"r"(a[2]),"r"(a[3]), "r"(b0),"r"(b1));
}
__device__ __forceinline__ void cp16(uint32_t saddr, const void* g, int sz){
    asm volatile("cp.async.cg.shared.global [%0], [%1], 16, %2;"
                 :: "r"(saddr), "l"(g), "r"(sz) : "memory");
}
__device__ __forceinline__ float warp_sum(float v){
    #pragma unroll
    for (int o = 16; o; o >>= 1) v += __shfl_xor_sync(0xffffffffu, v, o);
    return v;
}

// ---------------- fused fp32 -> fp16 weight conversion (all 4 weights) ----------------
__global__ void f2h_all(const float* __restrict__ s0, const float* __restrict__ s1,
                        const float* __restrict__ s2, const float* __restrict__ s3,
                        __half* __restrict__ d0, __half* __restrict__ d1,
                        __half* __restrict__ d2, __half* __restrict__ d3)
{
    int i = blockIdx.x*blockDim.x + threadIdx.x;
    if (i >= 393216) return;
    const float* s; __half* d; int off;
    if (i < 98304)        { s = s0; d = d0; off = i; }
    else if (i < 131072)  { s = s1; d = d1; off = i - 98304; }
    else if (i < 262144)  { s = s2; d = d2; off = i - 131072; }
    else                  { s = s3; d = d3; off = i - 262144; }
    float2 v = ((const float2*)s)[off];
    ((__half2*)d)[off] = __floats2half2_rn(v.x, v.y);
}

// ---------------- bias+mask table precompute: [variant][head][64][64] ----------------
__global__ void bias_table_kernel(const float* __restrict__ relt)
{
    int v = blockIdx.x >> 3, h = blockIdx.x & 7;
    bool rm = (v & 1) != 0, cm = (v & 2) != 0;
    float* dst = g_bias + (size_t)(v*NHEAD + h)*64*64;
    for (int e = threadIdx.x; e < 64*64; e += 128){
        int n = e >> 6, m = e & 63;
        float val;
        if (m >= NTOK){
            val = -20000.f;                 // pad col: exp -> 0
        } else {
            int nn = n < NTOK ? n : NTOK - 1;
            int in_ = nn/7, jn = nn - in_*7;
            int im  = m/7,  jm = m  - im*7;
            val = relt[((in_ - im + 6)*13 + (jn - jm + 6))*NHEAD + h];
            int rn = (rm ? (in_ < 4 ? 1 : 2) : 0)*3 + (cm ? (jn < 4 ? 1 : 2) : 0);
            int rmm= (rm ? (im  < 4 ? 1 : 2) : 0)*3 + (cm ? (jm  < 4 ? 1 : 2) : 0);
            if (rn != rmm) val -= 100.f;
        }
        dst[e] = val;
    }
}

// ---------------- LN1 + pad + shift + window partition (fp16 out) ----------------
__global__ __launch_bounds__(256) void ln1_window_kernel(
    const float* __restrict__ x, const float* __restrict__ g, const float* __restrict__ b)
{
    int warp = (blockIdx.x * blockDim.x + threadIdx.x) >> 5;
    int lane = threadIdx.x & 31;
    if (warp >= MW) return;
    int bi  = warp / (NWIN*NTOK);
    int rem = warp - bi*(NWIN*NTOK);
    int w = rem / NTOK, n = rem - w*NTOK;
    int r = w/9, c = w - r*9, i = n/7, j = n - i*7;
    int hs = r*7 + i + SSZ; if (hs >= HP) hs -= HP;
    int ws = c*7 + j + SSZ; if (ws >= HP) ws -= HP;

    __half2* dst = (__half2*)(g_xh + (size_t)warp*DIM);
    if (hs >= HH || ws >= WW) {
        __half2 z = __floats2half2_rn(0.f, 0.f);
        dst[lane*2] = z; dst[lane*2+1] = z;
        dst[64+lane*2] = z; dst[64+lane*2+1] = z;
        return;
    }
    const float4* src = (const float4*)(x + ((size_t)bi*(HH*WW) + hs*WW + ws)*DIM);
    float4 v0 = src[lane], v1 = src[lane+32];
    float s  = v0.x+v0.y+v0.z+v0.w + v1.x+v1.y+v1.z+v1.w;
    float ss = v0.x*v0.x+v0.y*v0.y+v0.z*v0.z+v0.w*v0.w
             + v1.x*v1.x+v1.y*v1.y+v1.z*v1.z+v1.w*v1.w;
    s  = warp_sum(s);
    ss = warp_sum(ss);
    float mu   = s * (1.f/DIM);
    float var  = ss * (1.f/DIM) - mu*mu;
    float rstd = rsqrtf(var + 1e-5f);
    const float4* gv = (const float4*)g;
    const float4* bv = (const float4*)b;
    float4 g0 = gv[lane], g1 = gv[lane+32], b0 = bv[lane], b1 = bv[lane+32];
    dst[lane*2]      = __floats2half2_rn((v0.x-mu)*rstd*g0.x + b0.x, (v0.y-mu)*rstd*g0.y + b0.y);
    dst[lane*2+1]    = __floats2half2_rn((v0.z-mu)*rstd*g0.z + b0.z, (v0.w-mu)*rstd*g0.w + b0.w);
    dst[64+lane*2]   = __floats2half2_rn((v1.x-mu)*rstd*g1.x + b1.x, (v1.y-mu)*rstd*g1.y + b1.y);
    dst[64+lane*2+1] = __floats2half2_rn((v1.z-mu)*rstd*g1.z + b1.z, (v1.w-mu)*rstd*g1.w + b1.w);
}

// ---------------- window reverse + unshift + residual + LN2 (fused) ----------------
__global__ __launch_bounds__(256) void resid_ln2_kernel(
    const float* __restrict__ x, const float* __restrict__ g, const float* __restrict__ b)
{
    int warp = (blockIdx.x * blockDim.x + threadIdx.x) >> 5;
    int lane = threadIdx.x & 31;
    if (warp >= MT) return;
    int bi = warp / (HH*WW), l = warp - bi*(HH*WW);
    int hh = l / WW, ww = l - hh*WW;
    int hs = hh + (HP - SSZ); if (hs >= HP) hs -= HP;
    int ws = ww + (HP - SSZ); if (ws >= HP) ws -= HP;
    int r = hs/7, i = hs - r*7, c = ws/7, j = ws - c*7;
    size_t m = ((size_t)bi*NWIN + r*9 + c)*NTOK + i*7 + j;

    const float4* xs = (const float4*)(x + (size_t)warp*DIM);
    const __half2* ps = (const __half2*)(g_projh + m*DIM);
    float4 a0 = xs[lane], a1 = xs[lane+32];
    __half2 h0 = ps[lane*2], h1 = ps[lane*2+1], h2 = ps[64+lane*2], h3 = ps[64+lane*2+1];
    float2 f0 = __half22float2(h0), f1 = __half22float2(h1);
    float2 f2 = __half22float2(h2), f3 = __half22float2(h3);
    a0.x += f0.x; a0.y += f0.y; a0.z += f1.x; a0.w += f1.y;
    a1.x += f2.x; a1.y += f2.y; a1.z += f3.x; a1.w += f3.y;
    float4* x1 = (float4*)(g_x1 + (size_t)warp*DIM);
    x1[lane] = a0; x1[lane+32] = a1;

    float s  = a0.x+a0.y+a0.z+a0.w + a1.x+a1.y+a1.z+a1.w;
    float ss = a0.x*a0.x+a0.y*a0.y+a0.z*a0.z+a0.w*a0.w
             + a1.x*a1.x+a1.y*a1.y+a1.z*a1.z+a1.w*a1.w;
    s  = warp_sum(s);
    ss = warp_sum(ss);
    float mu   = s * (1.f/DIM);
    float var  = ss * (1.f/DIM) - mu*mu;
    float rstd = rsqrtf(var + 1e-5f);
    const float4* gv = (const float4*)g;
    const float4* bv = (const float4*)b;
    float4 g0 = gv[lane], g1 = gv[lane+32], b0 = bv[lane], b1 = bv[lane+32];
    __half2* dst = (__half2*)(g_yh + (size_t)warp*DIM);
    dst[lane*2]      = __floats2half2_rn((a0.x-mu)*rstd*g0.x + b0.x, (a0.y-mu)*rstd*g0.y + b0.y);
    dst[lane*2+1]    = __floats2half2_rn((a0.z-mu)*rstd*g0.z + b0.z, (a0.w-mu)*rstd*g0.w + b0.w);
    dst[64+lane*2]   = __floats2half2_rn((a1.x-mu)*rstd*g1.x + b1.x, (a1.y-mu)*rstd*g1.y + b1.y);
    dst[64+lane*2+1] = __floats2half2_rn((a1.z-mu)*rstd*g1.z + b1.z, (a1.w-mu)*rstd*g1.w + b1.w);
}

// ---------------- fp16 mma.sync GEMM, BK=64, 3-stage cp.async + reg double-buffered frags ----------------
template<int EPI, typename TOUT>
__global__ __launch_bounds__(256, 2) void hgemm(
    const __half* __restrict__ A, const __half* __restrict__ B,
    const float* __restrict__ bias, const float* __restrict__ Res,
    TOUT* __restrict__ C, int M, int N, int K)
{
    extern __shared__ __half sm[];
    const int tid = threadIdx.x;
    const int m0 = blockIdx.y * BM, n0 = blockIdx.x * BN;
    const int lane = tid & 31, warp = tid >> 5;
    const int wm = (warp >> 1) * 32;     // 4 warps along M
    const int wn = (warp & 1) * 64;      // 2 warps along N
    const int g = lane >> 2, t = lane & 3;
    const int lr = lane & 15, lc = lane >> 4;

    float acc[2][8][4];
    #pragma unroll
    for (int mi = 0; mi < 2; mi++)
        #pragma unroll
        for (int ni = 0; ni < 8; ni++)
            #pragma unroll
            for (int q = 0; q < 4; q++) acc[mi][ni][q] = 0.f;

    const uint32_t sbase = smem_u32(sm);

    auto issue = [&](int kc, int s){
        const int k0 = kc * BK;
        #pragma unroll
        for (int i = 0; i < 4; i++){
            int f = tid + i*256;
            int row = f >> 3, q = f & 7;
            int gr = m0 + row;
            int cl = gr < M ? gr : (M - 1);
            const __half* src = A + (size_t)cl*K + k0 + q*8;
            cp16(sbase + (uint32_t)((s*STGH + row*AH + q*8)*2), src, gr < M ? 16 : 0);
        }
        #pragma unroll
        for (int i = 0; i < 4; i++){
            int f = tid + i*256;
            int row = f >> 4, q = f & 15;
            const __half* src = B + (size_t)(k0 + row)*N + n0 + q*8;
            cp16(sbase + (uint32_t)((s*STGH + BM*AH + row*BH + q*8)*2), src, 16);
        }
        asm volatile("cp.async.commit_group;" ::: "memory");
    };

    // fragment double buffers
    uint32_t af[2][2][4];
    uint32_t bf[2][4][4];

    const int nch = K / BK;
    issue(0, 0);
    if (nch > 1) issue(1, 1);
    int s = 0;
    for (int kc = 0; kc < nch; kc++){
        if (kc + 1 < nch){
            asm volatile("cp.async.wait_group 1;" ::: "memory");
        } else {
            asm volatile("cp.async.wait_group 0;" ::: "memory");
        }
        __syncthreads();
        if (kc + 2 < nch){
            int s2 = s + 2; if (s2 >= NSTAGE) s2 -= NSTAGE;
            issue(kc + 2, s2);
        }
        const uint32_t sa = sbase + (uint32_t)(s*STGH)*2;
        const uint32_t sb = sbase + (uint32_t)(s*STGH + BM*AH)*2;

        // preload kk=0 fragments into buffer 0
        #pragma unroll
        for (int mi = 0; mi < 2; mi++)
            ldsm4(af[0][mi], sa + (uint32_t)(((wm + mi*16 + lr)*AH + lc*8)*2));
        #pragma unroll
        for (int nb = 0; nb < 4; nb++)
            ldsm4t(bf[0][nb], sb + (uint32_t)((lr*BH + wn + nb*16 + lc*8)*2));

        #pragma unroll
        for (int kk = 0; kk < 4; kk++){
            const int cur = kk & 1, nxt = cur ^ 1;
            if (kk < 3){
                // prefetch next kk's fragments while current MMAs run
                #pragma unroll
                for (int mi = 0; mi < 2; mi++)
                    ldsm4(af[nxt][mi], sa + (uint32_t)(((wm + mi*16 + lr)*AH + (kk+1)*16 + lc*8)*2));
                #pragma unroll
                for (int nb = 0; nb < 4; nb++)
                    ldsm4t(bf[nxt][nb], sb + (uint32_t)((((kk+1)*16 + lr)*BH + wn + nb*16 + lc*8)*2));
            }
            #pragma unroll
            for (int nb = 0; nb < 4; nb++){
                mma16816(acc[0][nb*2+0], af[cur][0], bf[cur][nb][0], bf[cur][nb][1]);
                mma16816(acc[1][nb*2+0], af[cur][1], bf[cur][nb][0], bf[cur][nb][1]);
                mma16816(acc[0][nb*2+1], af[cur][0], bf[cur][nb][2], bf[cur][nb][3]);
                mma16816(acc[1][nb*2+1], af[cur][1], bf[cur][nb][2], bf[cur][nb][3]);
            }
        }
        if (++s >= NSTAGE) s = 0;
    }

    #pragma unroll
    for (int mi = 0; mi < 2; mi++){
        const int r0 = m0 + wm + mi*16 + g;
        #pragma unroll
        for (int half = 0; half < 2; half++){
            const int gr = r0 + half*8;
            if (gr < M){
                #pragma unroll
                for (int ni = 0; ni < 8; ni++){
                    const int col = n0 + wn + ni*8 + t*2;
                    float2 bb = *(const float2*)(bias + col);
                    float v0 = acc[mi][ni][half*2 + 0] + bb.x;
                    float v1 = acc[mi][ni][half*2 + 1] + bb.y;
                    if (EPI == 1){
                        v0 = 0.5f*v0*(1.f + erff(v0*0.70710678118654752f));
                        v1 = 0.5f*v1*(1.f + erff(v1*0.70710678118654752f));
                    }
                    if (EPI == 2){
                        float2 rr = *(const float2*)(Res + (size_t)gr*N + col);
                        v0 += rr.x; v1 += rr.y;
                    }
                    if (sizeof(TOUT) == 2){
                        *(__half2*)((__half*)C + (size_t)gr*N + col) = __floats2half2_rn(v0, v1);
                    } else {
                        *(float2*)((float*)C + (size_t)gr*N + col) = make_float2(v0, v1);
                    }
                }
            }
        }
    }
}

// ---------------- attention: fp16 MMA + table bias + register softmax ----------------
#define QH 40   // Q/K/V smem row stride (halves) — LDSM conflict-free
#define PH 72   // P smem row stride (halves)     — LDSM conflict-free
__global__ __launch_bounds__(128) void attn_kernel()
{
    __shared__ __half Qs[64][QH];
    __shared__ __half Ks[64][QH];
    __shared__ __half Vs[64][QH];
    __shared__ __half Ps[64][PH];

    const int tid = threadIdx.x;
    const int warp = tid >> 5, lane = tid & 31;
    const int g = lane >> 2, t = lane & 3;
    const int lr = lane & 15, lc = lane >> 4;
    const int wh  = blockIdx.x;
    const int win = wh >> 3;
    const int h   = wh & 7;

    const __half* base = g_qkvh + (size_t)win*NTOK*(3*DIM) + h*HD;
    for (int e = tid; e < 64*16; e += 128){
        int n = e >> 4, d = e & 15;
        __half2 q, k, v;
        if (n < NTOK){
            const __half2* row = (const __half2*)(base + (size_t)n*(3*DIM));
            q = row[d]; k = row[(DIM>>1) + d]; v = row[DIM + d];
        } else {
            q = __floats2half2_rn(0.f,0.f); k = q; v = q;
        }
        *(__half2*)&Qs[n][d*2] = q;
        *(__half2*)&Ks[n][d*2] = k;
        *(__half2*)&Vs[n][d*2] = v;
    }
    __syncthreads();

    // ---- S = Q @ K^T (batched LDSM then MMA)
    float accs[8][4];
    #pragma unroll
    for (int ni = 0; ni < 8; ni++)
        #pragma unroll
        for (int q = 0; q < 4; q++) accs[ni][q] = 0.f;

    const uint32_t qb = smem_u32(Qs), kb = smem_u32(Ks);
    #pragma unroll
    for (int kk = 0; kk < 2; kk++){
        uint32_t a[4];
        uint32_t b[4][4];
        ldsm4(a, qb + (uint32_t)(((16*warp + lr)*QH + kk*16 + lc*8)*2));
        #pragma unroll
        for (int nb = 0; nb < 4; nb++)
            ldsm4(b[nb], kb + (uint32_t)(((nb*16 + lr)*QH + kk*16 + lc*8)*2));
        #pragma unroll
        for (int nb = 0; nb < 4; nb++){
            mma16816(accs[nb*2+0], a, b[nb][0], b[nb][2]);
            mma16816(accs[nb*2+1], a, b[nb][1], b[nb][3]);
        }
    }

    // ---- bias table variant for this window
    const int w  = win % NWIN;
    const int wr = w / 9, wc = w - (w/9)*9;
    const int variant = (wr == 8 ? 1 : 0) | (wc == 8 ? 2 : 0);
    const float* tab = g_bias + (size_t)(variant*NHEAD + h)*64*64;
    const float scale = 0.17677669529663687f;   // 1/sqrt(32)

    // ---- epilogue + register softmax
    #pragma unroll
    for (int half = 0; half < 2; half++){
        const int row = 16*warp + half*8 + g;
        const float* trow = tab + row*64;
        float mx = -1e30f;
        #pragma unroll
        for (int ni = 0; ni < 8; ni++){
            int col = ni*8 + t*2;
            float2 bb = *(const float2*)(trow + col);
            float v0 = fmaf(accs[ni][half*2 + 0], scale, bb.x);
            float v1 = fmaf(accs[ni][half*2 + 1], scale, bb.y);
            accs[ni][half*2 + 0] = v0;
            accs[ni][half*2 + 1] = v1;
            mx = fmaxf(mx, fmaxf(v0, v1));
        }
        mx = fmaxf(mx, __shfl_xor_sync(0xffffffffu, mx, 1));
        mx = fmaxf(mx, __shfl_xor_sync(0xffffffffu, mx, 2));
        float sum = 0.f;
        #pragma unroll
        for (int ni = 0; ni < 8; ni++){
            float e0 = __expf(accs[ni][half*2 + 0] - mx);
            float e1 = __expf(accs[ni][half*2 + 1] - mx);
            accs[ni][half*2 + 0] = e0;
            accs[ni][half*2 + 1] = e1;
            sum += e0 + e1;
        }
        sum += __shfl_xor_sync(0xffffffffu, sum, 1);
        sum += __shfl_xor_sync(0xffffffffu, sum, 2);
        float inv = 1.f / sum;
        #pragma unroll
        for (int ni = 0; ni < 8; ni++){
            int col = ni*8 + t*2;
            *(__half2*)&Ps[row][col] = __floats2half2_rn(
                accs[ni][half*2 + 0]*inv, accs[ni][half*2 + 1]*inv);
        }
    }
    __syncthreads();

    // ---- O = P @ V (batched LDSM then MMA)
    float acco[4][4];
    #pragma unroll
    for (int ni = 0; ni < 4; ni++)
        #pragma unroll
        for (int q = 0; q < 4; q++) acco[ni][q] = 0.f;

    const uint32_t pb = smem_u32(Ps), vb = smem_u32(Vs);
    #pragma unroll
    for (int kk = 0; kk < 4; kk++){
        uint32_t a[4];
        uint32_t b[2][4];
        ldsm4(a, pb + (uint32_t)(((16*warp + lr)*PH + kk*16 + lc*8)*2));
        #pragma unroll
        for (int nb = 0; nb < 2; nb++)
            ldsm4t(b[nb], vb + (uint32_t)(((kk*16 + lr)*QH + nb*16 + lc*8)*2));
        #pragma unroll
        for (int nb = 0; nb < 2; nb++){
            mma16816(acco[nb*2+0], a, b[nb][0], b[nb][1]);
            mma16816(acco[nb*2+1], a, b[nb][2], b[nb][3]);
        }
    }

    // ---- write O (fp16)
    __half* out = g_atth + (size_t)win*NTOK*DIM + h*HD;
    #pragma unroll
    for (int ni = 0; ni < 4; ni++){
        #pragma unroll
        for (int half = 0; half < 2; half++){
            int row = 16*warp + half*8 + g;
            if (row < NTOK){
                int col = ni*8 + t*2;
                *(__half2*)(out + (size_t)row*DIM + col) =
                    __floats2half2_rn(acco[ni][half*2 + 0], acco[ni][half*2 + 1]);
            }
        }
    }
}

// ---------------- host launcher ----------------
extern "C" void kernel_launch(void* const* d_in, const int* in_sizes, int n_in,
                              void* d_out, int out_size)
{
    (void)in_sizes; (void)n_in; (void)out_size;
    const float* x      = (const float*)d_in[0];
    const float* g1     = (const float*)d_in[1];
    const float* b1     = (const float*)d_in[2];
    const float* w_qkv  = (const float*)d_in[3];
    const float* b_qkv  = (const float*)d_in[4];
    const float* relt   = (const float*)d_in[5];
    const float* w_proj = (const float*)d_in[6];
    const float* b_proj = (const float*)d_in[7];
    const float* g2     = (const float*)d_in[8];
    const float* b2     = (const float*)d_in[9];
    const float* w_fc1  = (const float*)d_in[10];
    const float* b_fc1  = (const float*)d_in[11];
    const float* w_fc2  = (const float*)d_in[12];
    const float* b_fc2  = (const float*)d_in[13];
    float* out = (float*)d_out;

    __half *p_xh, *p_qkvh, *p_atth, *p_projh, *p_yh, *p_hh, *p_wq, *p_wp, *p_w1, *p_w2;
    float *p_x1;
    cudaGetSymbolAddress((void**)&p_xh,  g_xh);
    cudaGetSymbolAddress((void**)&p_qkvh,g_qkvh);
    cudaGetSymbolAddress((void**)&p_atth,g_atth);
    cudaGetSymbolAddress((void**)&p_projh,g_projh);
    cudaGetSymbolAddress((void**)&p_x1,  g_x1);
    cudaGetSymbolAddress((void**)&p_yh,  g_yh);
    cudaGetSymbolAddress((void**)&p_hh,  g_hh);
    cudaGetSymbolAddress((void**)&p_wq,  g_wq);
    cudaGetSymbolAddress((void**)&p_wp,  g_wp);
    cudaGetSymbolAddress((void**)&p_w1,  g_w1);
    cudaGetSymbolAddress((void**)&p_w2,  g_w2);

    cudaFuncSetAttribute(hgemm<0,__half>, cudaFuncAttributeMaxDynamicSharedMemorySize, GEMM_SMEM);
    cudaFuncSetAttribute(hgemm<1,__half>, cudaFuncAttributeMaxDynamicSharedMemorySize, GEMM_SMEM);
    cudaFuncSetAttribute(hgemm<2,float>,  cudaFuncAttributeMaxDynamicSharedMemorySize, GEMM_SMEM);

    // 0) weights -> fp16; attention bias table
    f2h_all<<<(393216 + 255)/256, 256>>>(w_qkv, w_proj, w_fc1, w_fc2, p_wq, p_wp, p_w1, p_w2);
    bias_table_kernel<<<4*NHEAD, 128>>>(relt);

    // 1) LN1 + pad + shift + window partition (fp16)
    ln1_window_kernel<<<(MW*32 + 255)/256, 256>>>(x, g1, b1);

    // 2) QKV GEMM [MW,256]x[256,768] -> fp16
    hgemm<0,__half><<<dim3(768/BN, (MW + BM - 1)/BM), 256, GEMM_SMEM>>>(
        p_xh, p_wq, b_qkv, (const float*)0, p_qkvh, MW, 768, 256);

    // 3) attention (fp16 MMA, table bias, register softmax) -> fp16
    attn_kernel<<<BATCH*NWIN*NHEAD, 128>>>();

    // 4) proj GEMM [MW,256]x[256,256] -> fp16
    hgemm<0,__half><<<dim3(256/BN, (MW + BM - 1)/BM), 256, GEMM_SMEM>>>(
        p_atth, p_wp, b_proj, (const float*)0, p_projh, MW, 256, 256);

    // 5) window reverse + unshift + residual + LN2
    resid_ln2_kernel<<<(MT*32 + 255)/256, 256>>>(x, g2, b2);

    // 6) fc1 + GELU [MT,256]x[256,1024] -> fp16
    hgemm<1,__half><<<dim3(1024/BN, MT/BM), 256, GEMM_SMEM>>>(
        p_yh, p_w1, b_fc1, (const float*)0, p_hh, MT, 1024, 256);

    // 7) fc2 + bias + residual [MT,1024]x[1024,256] -> out fp32
    hgemm<2,float><<<dim3(256/BN, MT/BM), 256, GEMM_SMEM>>>(
        p_hh, p_w2, b_fc2, p_x1, out, MT, 256, 1024);
}